// round 10
// baseline (speedup 1.0000x reference)
#include <cuda_runtime.h>
#include <cuda_fp16.h>
#include <math.h>

#define HW   64800
#define E_   256
#define NLAY 4
#define LM_  90
#define MM_  91
#define HID_ 512
#define H_   180
#define W_   360
#define STG  4
#define SMEMSZ (STG * (128 * 40 + 32 * 136) * 2)

// ---------------- scratch (device globals) ----------------
__device__ __half g_P_h[E_ * HW];          // fp16 inner-skip product (side stream)
__device__ __half g_hA_h[(E_ + 2) * HW];   // fp16 h (residual carrier); rows 256,257 = raw x
__device__ __half g_hB_h[E_ * HW];
__device__ __half g_t_h [HID_ * HW];
__device__ __half g_xfh [MM_ * H_ * 512];  // rfft out: [m][y][2c+ri]
__device__ __half g_cfh [LM_ * 512 * 96];  // legfwd out: [l][2c+ri][m] (m pad 96)
__device__ __half g_cf2h[MM_ * 512 * 96];  // spectral out: [m][o2][l] (l pad 96)
__device__ __half g_xf2h[46080 * 184];     // leginv out: [(o,y)][2m+ri] (pad 184)
__device__ __half g_F_h [W_ * 184];        // rfft DFT [x][2m+ri]
__device__ __half g_Gi_h[182 * W_];        // irfft DFT [2m+ri][x]
__device__ __half g_legf_h[MM_ * LM_ * 184 + 64 * 184];
__device__ __half g_legi_h[MM_ * LM_ * 184];
__device__ __half g_A2[NLAY][LM_ * 512 * 512];  // spectral fp16 weights, all layers
// fp16 weights
__device__ __half g_w_enc2[E_ * E_];
__device__ __half g_w_inner[NLAY * E_ * E_];
__device__ __half g_w_mlp1[NLAY * HID_ * E_];
__device__ __half g_w_mlp2[NLAY * E_ * HID_];
__device__ __half g_w_dec1[E_ * 264];

__device__ __forceinline__ float gelu_f(float v) {
    return 0.5f * v * (1.0f + erff(v * 0.7071067811865475f));
}
__device__ __forceinline__ unsigned smem_u32(const void* p) {
    return (unsigned)__cvta_generic_to_shared(p);
}
__device__ __forceinline__ void cp16(void* s, const void* g, bool p) {
    unsigned sa = smem_u32(s);
    asm volatile("cp.async.cg.shared.global [%0],[%1],16,%2;\n"
                 :: "r"(sa), "l"(g), "r"(p ? 16 : 0));
}

// ---------------- DFT tables ----------------
__global__ void k_init_tables() {
    int idx = blockIdx.x * blockDim.x + threadIdx.x;
    if (idx < W_ * 184) {
        int x = idx / 184, col = idx % 184;
        float v = 0.f;
        if (col < 182) {
            int m = col >> 1, ri = col & 1;
            int r = (m * x) % W_;
            double s, c;
            sincospi((double)r / 180.0, &s, &c);
            v = ri ? (float)(-s) : (float)c;
        }
        g_F_h[idx] = __float2half(v);
    }
    if (idx < 182 * W_) {
        int k = idx / W_, x = idx % W_;
        int m = k >> 1, ri = k & 1;
        int r = (m * x) % W_;
        double s, c;
        sincospi((double)r / 180.0, &s, &c);
        double sc = (m == 0) ? (1.0 / 360.0) : (2.0 / 360.0);
        g_Gi_h[idx] = __float2half(ri ? (float)(-sc * s) : (float)(sc * c));
    }
}

__global__ void k_zero_cfh() {
    int i = blockIdx.x * blockDim.x + threadIdx.x;
    if (i < LM_ * 512 * 96 / 8) ((uint4*)g_cfh)[i] = make_uint4(0, 0, 0, 0);
}

__global__ void k_cast_leg(const float* __restrict__ s, __half* __restrict__ d) {
    int i = blockIdx.x * blockDim.x + threadIdx.x;
    if (i >= MM_ * LM_ * 184) return;
    int col = i % 184, row = i / 184;
    d[i] = (col < H_) ? __float2half(s[row * H_ + col]) : __half(0);
}

// transpose-tiled spectral weight build
__global__ void k_buildA2_t(const float* __restrict__ wr, const float* __restrict__ wi, int slot) {
    int o  = blockIdx.z;
    int c0 = blockIdx.x * 32;
    int l0 = blockIdx.y * 32;
    __shared__ float sr[32][33], si[32][33];
    int tx = threadIdx.x, ty = threadIdx.y;
    #pragma unroll
    for (int i = 0; i < 32; i += 8) {
        int c = c0 + ty + i, l = l0 + tx;
        long base = ((long)o * E_ + c) * LM_ + l;
        bool ok = (l < LM_);
        sr[ty + i][tx] = ok ? wr[base] : 0.f;
        si[ty + i][tx] = ok ? wi[base] : 0.f;
    }
    __syncthreads();
    int c = c0 + tx;
    #pragma unroll
    for (int j = 0; j < 32; j += 8) {
        int l = l0 + ty + j;
        if (l >= LM_) break;
        float r  = sr[tx][ty + j];
        float im = si[tx][ty + j];
        long b0 = ((long)l * 512 + o) * 512 + 2 * c;
        long b1 = ((long)l * 512 + o + 256) * 512 + 2 * c;
        *(__half2*)&g_A2[slot][b0] = __floats2half2_rn(r, -im);
        *(__half2*)&g_A2[slot][b1] = __floats2half2_rn(im, r);
    }
}

// ---------------- casts ----------------
__global__ void k_castw(const float* __restrict__ s, __half* __restrict__ d, int n) {
    int i = blockIdx.x * blockDim.x + threadIdx.x;
    if (i < n) d[i] = __float2half(s[i]);
}
__global__ void k_cast_dec1(const float* __restrict__ s) {
    int i = blockIdx.x * blockDim.x + threadIdx.x;
    if (i >= E_ * 264) return;
    int r = i / 264, c = i % 264;
    g_w_dec1[i] = (c < 258) ? __float2half(s[r * 258 + c]) : __half(0);
}
__global__ void k_castx(const float* __restrict__ x) {
    int i = blockIdx.x * blockDim.x + threadIdx.x;
    if (i < 2 * HW) g_hA_h[E_ * HW + i] = __float2half(x[i]);
}

__global__ void k_enc1(const float* __restrict__ x, const float* __restrict__ w) {
    int p = blockIdx.x * blockDim.x + threadIdx.x;
    if (p >= HW) return;
    float x0 = x[p], x1 = x[HW + p];
    #pragma unroll 4
    for (int e = 0; e < E_; e++) {
        float v = w[2 * e] * x0 + w[2 * e + 1] * x1;
        g_hB_h[e * HW + p] = __float2half(gelu_f(v));
    }
}

// ---------------- fp16 tensor-core GEMM, 4-stage cp.async (R6 structure) ----------------
// MODE 0: std epilogue. 1: rfft scatter -> g_xfh. 2: legfwd -> g_cfh.
// 3: spectral -> g_cf2h. 4: leginv -> g_xf2h.
// ADDH: add fp16 ADDh tensor (half2 reads) in MODE 0.
template <int MODE, bool GELU, bool ADDF, bool WF32, bool WF16, bool ADDH = false>
__global__ __launch_bounds__(256, 2) void k_hgemm(
    const __half* __restrict__ A, const __half* __restrict__ B,
    float* __restrict__ C, const float* __restrict__ ADD, __half* __restrict__ Ch,
    const __half* __restrict__ ADDh,
    int M, int N, int K, int lda, long sA, long sB, long sC) {
    extern __shared__ __half dsm[];
    typedef __half (*AsT)[128][40];
    typedef __half (*BsT)[32][136];
    AsT As = (AsT)dsm;
    BsT Bs = (BsT)(dsm + STG * 128 * 40);
    const int tid = threadIdx.x, lane = tid & 31, wid = tid >> 5;
    const int wm = wid >> 2, wn = wid & 3;
    const int bm = blockIdx.y * 128, bn = blockIdx.x * 128;
    const int z = blockIdx.z;
    A += (long)z * sA;
    B += (long)z * sB;
    if (WF32 && MODE == 0) C += (long)z * sC;

    const int r_a = tid >> 1, off_a = (tid & 1) * 16;
    #define LOAD_STAGE(k0, buf)                                                     \
        {                                                                           \
            const __half* pA = A + (long)(bm + r_a) * lda + (k0) + off_a;           \
            bool pa0 = ((k0) + off_a + 8  <= lda);                                  \
            bool pa1 = ((k0) + off_a + 16 <= lda);                                  \
            cp16(&As[buf][r_a][off_a],     pa0 ? pA     : A, pa0);                  \
            cp16(&As[buf][r_a][off_a + 8], pa1 ? pA + 8 : A, pa1);                  \
            _Pragma("unroll")                                                       \
            for (int i = 0; i < 2; i++) {                                           \
                int idx = tid + i * 256;                                            \
                int kk = idx >> 4, noff = (idx & 15) * 8;                           \
                int gk = (k0) + kk, gn = bn + noff;                                 \
                bool pb = (gk < K && gn + 8 <= N);                                  \
                cp16(&Bs[buf][kk][noff], pb ? B + (long)gk * N + gn : B, pb);       \
            }                                                                       \
            asm volatile("cp.async.commit_group;\n" ::);                            \
        }

    float acc[4][4][4];
    #pragma unroll
    for (int i = 0; i < 4; i++)
        #pragma unroll
        for (int j = 0; j < 4; j++)
            #pragma unroll
            for (int q = 0; q < 4; q++) acc[i][j][q] = 0.f;

    LOAD_STAGE(0, 0)
    LOAD_STAGE(32, 1)
    LOAD_STAGE(64, 2)

    const int nslab = (K + 31) / 32;
    for (int it = 0; it < nslab; it++) {
        asm volatile("cp.async.wait_group 2;\n" ::);
        __syncthreads();
        const int buf = it & 3;
        #pragma unroll
        for (int ks = 0; ks < 32; ks += 16) {
            unsigned a[4][4], b[4][2];
            #pragma unroll
            for (int mt = 0; mt < 4; mt++) {
                unsigned addr = smem_u32(&As[buf][wm * 64 + mt * 16 + (lane & 15)][ks + 8 * (lane >> 4)]);
                asm volatile("ldmatrix.sync.aligned.m8n8.x4.shared.b16 {%0,%1,%2,%3},[%4];"
                             : "=r"(a[mt][0]), "=r"(a[mt][1]), "=r"(a[mt][2]), "=r"(a[mt][3])
                             : "r"(addr));
            }
            #pragma unroll
            for (int nt = 0; nt < 4; nt++) {
                unsigned addr = smem_u32(&Bs[buf][ks + (lane & 15)][wn * 32 + nt * 8]);
                asm volatile("ldmatrix.sync.aligned.m8n8.x2.trans.shared.b16 {%0,%1},[%2];"
                             : "=r"(b[nt][0]), "=r"(b[nt][1])
                             : "r"(addr));
            }
            #pragma unroll
            for (int mt = 0; mt < 4; mt++)
                #pragma unroll
                for (int nt = 0; nt < 4; nt++)
                    asm volatile(
                        "mma.sync.aligned.m16n8k16.row.col.f32.f16.f16.f32 "
                        "{%0,%1,%2,%3},{%4,%5,%6,%7},{%8,%9},{%0,%1,%2,%3};"
                        : "+f"(acc[mt][nt][0]), "+f"(acc[mt][nt][1]),
                          "+f"(acc[mt][nt][2]), "+f"(acc[mt][nt][3])
                        : "r"(a[mt][0]), "r"(a[mt][1]), "r"(a[mt][2]), "r"(a[mt][3]),
                          "r"(b[nt][0]), "r"(b[nt][1]));
        }
        __syncthreads();
        int k0n = (it + 3) * 32;
        if (k0n < K) {
            LOAD_STAGE(k0n, (it + 3) & 3)
        } else {
            asm volatile("cp.async.commit_group;\n" ::);
        }
    }
    #undef LOAD_STAGE

    const int g = lane >> 2, tq = lane & 3;
    #pragma unroll
    for (int mt = 0; mt < 4; mt++) {
        #pragma unroll
        for (int hh = 0; hh < 2; hh++) {
            int gm = bm + wm * 64 + mt * 16 + g + hh * 8;
            float vv0, vv1;
            #pragma unroll
            for (int nt = 0; nt < 4; nt++) {
                int gn = bn + wn * 32 + nt * 8 + tq * 2;
                vv0 = acc[mt][nt][hh * 2 + 0];
                vv1 = acc[mt][nt][hh * 2 + 1];
                if (MODE == 1) {
                    if (gn < 2 * MM_) {
                        int m = gn >> 1;
                        int c = gm / H_, y = gm - c * H_;
                        *(__half2*)&g_xfh[(long)m * (H_ * 512) + y * 512 + 2 * c] =
                            __floats2half2_rn(vv0, vv1);
                    }
                } else if (MODE == 2) {
                    if (gm < LM_) {
                        long base = ((long)gm * 512 + gn) * 96 + z;
                        g_cfh[base]      = __float2half(vv0);
                        g_cfh[base + 96] = __float2half(vv1);
                    }
                } else if (MODE == 3) {
                    if (gn < MM_)
                        g_cf2h[((long)gn * 512 + gm) * 96 + z] = __float2half(vv0);
                    if (gn + 1 < MM_)
                        g_cf2h[((long)(gn + 1) * 512 + gm) * 96 + z] = __float2half(vv1);
                } else if (MODE == 4) {
                    int oo = gm & 255, ri = gm >> 8;
                    if (gn < H_) {
                        long addr = ((long)oo * H_ + gn) * 184 + 2 * z + ri;
                        g_xf2h[addr] = __float2half(vv0);
                        if (gn + 1 < H_) g_xf2h[addr + 184] = __float2half(vv1);
                    }
                } else {
                    if (gm >= M || gn >= N) continue;
                    if (GELU) { vv0 = gelu_f(vv0); vv1 = gelu_f(vv1); }
                    if (ADDF) {
                        float2 ad = *(const float2*)&ADD[(long)gm * N + gn];
                        vv0 += ad.x; vv1 += ad.y;
                    }
                    if (ADDH) {
                        __half2 ah = *(const __half2*)&ADDh[(long)gm * N + gn];
                        float2 af = __half22float2(ah);
                        vv0 += af.x; vv1 += af.y;
                    }
                    if (WF32) *(float2*)&C[(long)gm * N + gn] = make_float2(vv0, vv1);
                    if (WF16) *(__half2*)&Ch[(long)gm * N + gn] = __floats2half2_rn(vv0, vv1);
                }
            }
        }
    }
}

__global__ void k_dec2(const float* __restrict__ w, float* __restrict__ out) {
    int p = blockIdx.x * blockDim.x + threadIdx.x;
    if (p >= HW) return;
    float a0 = 0.f, a1 = 0.f;
    #pragma unroll 4
    for (int c = 0; c < E_; c++) {
        float v = __half2float(g_t_h[c * HW + p]);
        a0 += w[c] * v;
        a1 += w[E_ + c] * v;
    }
    out[p] = a0;
    out[HW + p] = a1;
}

extern "C" void kernel_launch(void* const* d_in, const int* in_sizes, int n_in,
                              void* d_out, int out_size) {
    const float* x        = (const float*)d_in[0];
    const float* enc_w1   = (const float*)d_in[1];
    const float* enc_w2   = (const float*)d_in[2];
    const float* pos      = (const float*)d_in[3];
    const float* leg_fwd  = (const float*)d_in[4];
    const float* leg_inv  = (const float*)d_in[5];
    const float* w_spec_r = (const float*)d_in[6];
    const float* w_spec_i = (const float*)d_in[7];
    const float* w_inner  = (const float*)d_in[8];
    const float* w_mlp1   = (const float*)d_in[9];
    const float* w_mlp2   = (const float*)d_in[10];
    const float* dec_w1   = (const float*)d_in[11];
    const float* dec_w2   = (const float*)d_in[12];
    float* out = (float*)d_out;

    __half *Ph, *hAh, *hBh, *tH, *wEnc2, *wInn, *wM1, *wM2, *wDec1;
    __half *Fh, *Gih, *xfh, *cfh, *cf2h, *xf2h, *legfH, *legiH, *A2;
    cudaGetSymbolAddress((void**)&Ph, g_P_h);
    cudaGetSymbolAddress((void**)&hAh, g_hA_h);
    cudaGetSymbolAddress((void**)&hBh, g_hB_h);
    cudaGetSymbolAddress((void**)&tH, g_t_h);
    cudaGetSymbolAddress((void**)&wEnc2, g_w_enc2);
    cudaGetSymbolAddress((void**)&wInn, g_w_inner);
    cudaGetSymbolAddress((void**)&wM1, g_w_mlp1);
    cudaGetSymbolAddress((void**)&wM2, g_w_mlp2);
    cudaGetSymbolAddress((void**)&wDec1, g_w_dec1);
    cudaGetSymbolAddress((void**)&Fh, g_F_h);
    cudaGetSymbolAddress((void**)&Gih, g_Gi_h);
    cudaGetSymbolAddress((void**)&xfh, g_xfh);
    cudaGetSymbolAddress((void**)&cfh, g_cfh);
    cudaGetSymbolAddress((void**)&cf2h, g_cf2h);
    cudaGetSymbolAddress((void**)&xf2h, g_xf2h);
    cudaGetSymbolAddress((void**)&legfH, g_legf_h);
    cudaGetSymbolAddress((void**)&legiH, g_legi_h);
    cudaGetSymbolAddress((void**)&A2, g_A2);

    cudaFuncSetAttribute(k_hgemm<0, false, true,  false, true >, cudaFuncAttributeMaxDynamicSharedMemorySize, SMEMSZ);
    cudaFuncSetAttribute(k_hgemm<0, true,  false, false, true >, cudaFuncAttributeMaxDynamicSharedMemorySize, SMEMSZ);
    cudaFuncSetAttribute(k_hgemm<0, false, false, false, true >, cudaFuncAttributeMaxDynamicSharedMemorySize, SMEMSZ);
    cudaFuncSetAttribute(k_hgemm<0, false, false, false, true, true>, cudaFuncAttributeMaxDynamicSharedMemorySize, SMEMSZ);
    cudaFuncSetAttribute(k_hgemm<1, false, false, false, false>, cudaFuncAttributeMaxDynamicSharedMemorySize, SMEMSZ);
    cudaFuncSetAttribute(k_hgemm<2, false, false, false, false>, cudaFuncAttributeMaxDynamicSharedMemorySize, SMEMSZ);
    cudaFuncSetAttribute(k_hgemm<3, false, false, false, false>, cudaFuncAttributeMaxDynamicSharedMemorySize, SMEMSZ);
    cudaFuncSetAttribute(k_hgemm<4, false, false, false, false>, cudaFuncAttributeMaxDynamicSharedMemorySize, SMEMSZ);

    static cudaStream_t s1 = nullptr, s2 = nullptr;
    static cudaEvent_t evRoot, evInit, evW, evA2[NLAY], evL[NLAY], evP[NLAY];
    if (!s1) {
        cudaStreamCreateWithFlags(&s1, cudaStreamNonBlocking);
        cudaStreamCreateWithFlags(&s2, cudaStreamNonBlocking);
        cudaEventCreateWithFlags(&evRoot, cudaEventDisableTiming);
        cudaEventCreateWithFlags(&evInit, cudaEventDisableTiming);
        cudaEventCreateWithFlags(&evW, cudaEventDisableTiming);
        for (int i = 0; i < NLAY; i++) {
            cudaEventCreateWithFlags(&evA2[i], cudaEventDisableTiming);
            cudaEventCreateWithFlags(&evL[i], cudaEventDisableTiming);
            cudaEventCreateWithFlags(&evP[i], cudaEventDisableTiming);
        }
    }

    const int NB = (HW + 127) / 128;   // 507
    dim3 gE(NB, E_ / 128);
    dim3 gH(NB, HID_ / 128);
    dim3 gRF(2, 360);
    dim3 gLF(4, 1, MM_);
    dim3 gSP(1, 4, LM_);
    dim3 gLI(2, 4, MM_);
    dim3 gIR(3, 360);
    dim3 gB2(8, 3, 256), bB2(32, 8);

    // ---- fork init stream ----
    cudaEventRecord(evRoot, 0);
    cudaStreamWaitEvent(s1, evRoot, 0);
    k_castw<<<(E_ * E_ + 255) / 256, 256, 0, s1>>>(enc_w2, wEnc2, E_ * E_);
    cudaEventRecord(evW, s1);
    k_castw<<<(NLAY * E_ * E_ + 255) / 256, 256, 0, s1>>>(w_inner, wInn, NLAY * E_ * E_);
    k_castw<<<(NLAY * HID_ * E_ + 255) / 256, 256, 0, s1>>>(w_mlp1, wM1, NLAY * HID_ * E_);
    k_castw<<<(NLAY * E_ * HID_ + 255) / 256, 256, 0, s1>>>(w_mlp2, wM2, NLAY * E_ * HID_);
    k_init_tables<<<(W_ * 184 + 255) / 256, 256, 0, s1>>>();
    k_zero_cfh<<<(LM_ * 512 * 96 / 8 + 255) / 256, 256, 0, s1>>>();
    k_cast_leg<<<(MM_ * LM_ * 184 + 255) / 256, 256, 0, s1>>>(leg_fwd, legfH);
    k_cast_leg<<<(MM_ * LM_ * 184 + 255) / 256, 256, 0, s1>>>(leg_inv, legiH);
    k_cast_dec1<<<(E_ * 264 + 255) / 256, 256, 0, s1>>>(dec_w1);
    k_castx<<<(2 * HW + 255) / 256, 256, 0, s1>>>(x);
    cudaEventRecord(evInit, s1);
    for (int i = 0; i < NLAY; i++) {
        k_buildA2_t<<<gB2, bB2, 0, s1>>>(w_spec_r + (long)i * E_ * E_ * LM_,
                                         w_spec_i + (long)i * E_ * E_ * LM_, i);
        cudaEventRecord(evA2[i], s1);
    }

    // ---- main: encoder ----
    k_enc1<<<(HW + 255) / 256, 256>>>(x, enc_w1);
    cudaStreamWaitEvent(0, evW, 0);
    // hAh = fp16( enc_w2 @ hBh + pos )   (fp16-only write; pos read fp32)
    k_hgemm<0, false, true, false, true><<<gE, 256, SMEMSZ>>>(wEnc2, hBh, nullptr, pos, hAh,
                                                              nullptr, E_, HW, E_, E_, 0, 0, 0);
    cudaEventRecord(evL[0], 0);
    cudaStreamWaitEvent(0, evInit, 0);

    for (int i = 0; i < NLAY; i++) {
        // side s2: Ph = fp16( w_inner[i] @ hAh ), concurrent with spectral chain
        cudaStreamWaitEvent(s2, evL[i], 0);
        if (i == 0) cudaStreamWaitEvent(s2, evInit, 0);
        k_hgemm<0, false, false, false, true><<<gE, 256, SMEMSZ, s2>>>(
            wInn + (long)i * E_ * E_, hAh, nullptr, nullptr, Ph, nullptr,
            E_, HW, E_, E_, 0, 0, 0);
        cudaEventRecord(evP[i], s2);

        // main: spectral chain
        k_hgemm<1, false, false, false, false><<<gRF, 256, SMEMSZ>>>(
            hAh, Fh, nullptr, nullptr, nullptr, nullptr, 46080, 184, W_, W_, 0, 0, 0);
        k_hgemm<2, false, false, false, false><<<gLF, 256, SMEMSZ>>>(
            legfH, xfh, nullptr, nullptr, nullptr, nullptr, LM_, 512, H_, 184,
            (long)LM_ * 184, (long)H_ * 512, 0);
        cudaStreamWaitEvent(0, evA2[i], 0);
        k_hgemm<3, false, false, false, false><<<gSP, 256, SMEMSZ>>>(
            A2 + (long)i * LM_ * 512 * 512, cfh, nullptr, nullptr, nullptr, nullptr,
            512, 96, 512, 512, (long)512 * 512, (long)512 * 96, 0);
        k_hgemm<4, false, false, false, false><<<gLI, 256, SMEMSZ>>>(
            cf2h, legiH, nullptr, nullptr, nullptr, nullptr, 512, 184, LM_, 96,
            (long)512 * 96, (long)LM_ * 184, 0);
        // irfft + inner skip fused: hBh = fp16( irfft(xf2h) + Ph )
        cudaStreamWaitEvent(0, evP[i], 0);
        k_hgemm<0, false, false, false, true, true><<<gIR, 256, SMEMSZ>>>(
            xf2h, Gih, nullptr, nullptr, hBh, Ph, 46080, W_, 182, 184, 0, 0, 0);
        // t_h = fp16( gelu(w_mlp1 @ hBh) )
        k_hgemm<0, true, false, false, true><<<gH, 256, SMEMSZ>>>(
            wM1 + (long)i * HID_ * E_, hBh, nullptr, nullptr, tH, nullptr,
            HID_, HW, E_, E_, 0, 0, 0);
        // hAh = fp16( w_mlp2 @ t_h + hAh )   (in-place fp16 residual carry)
        k_hgemm<0, false, false, false, true, true><<<gE, 256, SMEMSZ>>>(
            wM2 + (long)i * E_ * HID_, tH, nullptr, nullptr, hAh, hAh,
            E_, HW, HID_, HID_, 0, 0, 0);
        if (i + 1 < NLAY) cudaEventRecord(evL[i + 1], 0);
    }

    k_hgemm<0, true, false, false, true><<<gE, 256, SMEMSZ>>>(wDec1, hAh, nullptr, nullptr,
                                                              tH, nullptr, E_, HW, 258, 264, 0, 0, 0);
    k_dec2<<<(HW + 255) / 256, 256>>>(dec_w2, out);
}

// round 11
// speedup vs baseline: 1.0395x; 1.0395x over previous
#include <cuda_runtime.h>
#include <cuda_fp16.h>
#include <math.h>

#define HW   64800
#define E_   256
#define NLAY 4
#define LM_  90
#define MM_  91
#define HID_ 512
#define H_   180
#define W_   360
#define STG  4
#define SMEMSZ (STG * (128 * 40 + 32 * 136) * 2)

// ---------------- scratch (device globals) ----------------
__device__ float  g_hA[E_ * HW];           // fp32 h (residual)
__device__ __half g_P_h[E_ * HW];          // fp16 inner-skip product (side stream)
__device__ __half g_hA_h[(E_ + 2) * HW];   // fp16 h; rows 256,257 = raw x
__device__ __half g_hB_h[E_ * HW];
__device__ __half g_t_h [HID_ * HW];
__device__ __half g_xfh [MM_ * H_ * 512];  // rfft out: [m][y][2c+ri]
__device__ __half g_cfh [LM_ * 512 * 96];  // legfwd out: [l][2c+ri][m] (m pad 96)
__device__ __half g_cf2h[MM_ * 512 * 96];  // spectral out: [m][o2][l] (l pad 96)
__device__ __half g_xf2h[46080 * 184];     // leginv out: [(o,y)][2m+ri] (pad 184)
__device__ __half g_F_h [W_ * 184];        // rfft DFT [x][2m+ri]
__device__ __half g_Gi_h[182 * W_];        // irfft DFT [2m+ri][x]
__device__ __half g_legf_h[MM_ * LM_ * 184 + 64 * 184];
__device__ __half g_legi_h[MM_ * LM_ * 184];
__device__ __half g_A2[NLAY][LM_ * 512 * 512];  // spectral fp16 weights, all layers
// fp16 weights
__device__ __half g_w_enc2[E_ * E_];
__device__ __half g_w_inner[NLAY * E_ * E_];
__device__ __half g_w_mlp1[NLAY * HID_ * E_];
__device__ __half g_w_mlp2[NLAY * E_ * HID_];
__device__ __half g_w_dec1[E_ * 264];

__device__ __forceinline__ float gelu_f(float v) {
    return 0.5f * v * (1.0f + erff(v * 0.7071067811865475f));
}
__device__ __forceinline__ unsigned smem_u32(const void* p) {
    return (unsigned)__cvta_generic_to_shared(p);
}
__device__ __forceinline__ void cp16(void* s, const void* g, bool p) {
    unsigned sa = smem_u32(s);
    asm volatile("cp.async.cg.shared.global [%0],[%1],16,%2;\n"
                 :: "r"(sa), "l"(g), "r"(p ? 16 : 0));
}

// ---------------- DFT tables ----------------
__global__ void k_init_tables() {
    int idx = blockIdx.x * blockDim.x + threadIdx.x;
    if (idx < W_ * 184) {
        int x = idx / 184, col = idx % 184;
        float v = 0.f;
        if (col < 182) {
            int m = col >> 1, ri = col & 1;
            int r = (m * x) % W_;
            double s, c;
            sincospi((double)r / 180.0, &s, &c);
            v = ri ? (float)(-s) : (float)c;
        }
        g_F_h[idx] = __float2half(v);
    }
    if (idx < 182 * W_) {
        int k = idx / W_, x = idx % W_;
        int m = k >> 1, ri = k & 1;
        int r = (m * x) % W_;
        double s, c;
        sincospi((double)r / 180.0, &s, &c);
        double sc = (m == 0) ? (1.0 / 360.0) : (2.0 / 360.0);
        g_Gi_h[idx] = __float2half(ri ? (float)(-sc * s) : (float)(sc * c));
    }
}

__global__ void k_zero_cfh() {
    int i = blockIdx.x * blockDim.x + threadIdx.x;
    if (i < LM_ * 512 * 96 / 8) ((uint4*)g_cfh)[i] = make_uint4(0, 0, 0, 0);
}

__global__ void k_cast_leg(const float* __restrict__ s, __half* __restrict__ d) {
    int i = blockIdx.x * blockDim.x + threadIdx.x;
    if (i >= MM_ * LM_ * 184) return;
    int col = i % 184, row = i / 184;
    d[i] = (col < H_) ? __float2half(s[row * H_ + col]) : __half(0);
}

// transpose-tiled spectral weight build
__global__ void k_buildA2_t(const float* __restrict__ wr, const float* __restrict__ wi, int slot) {
    int o  = blockIdx.z;
    int c0 = blockIdx.x * 32;
    int l0 = blockIdx.y * 32;
    __shared__ float sr[32][33], si[32][33];
    int tx = threadIdx.x, ty = threadIdx.y;
    #pragma unroll
    for (int i = 0; i < 32; i += 8) {
        int c = c0 + ty + i, l = l0 + tx;
        long base = ((long)o * E_ + c) * LM_ + l;
        bool ok = (l < LM_);
        sr[ty + i][tx] = ok ? wr[base] : 0.f;
        si[ty + i][tx] = ok ? wi[base] : 0.f;
    }
    __syncthreads();
    int c = c0 + tx;
    #pragma unroll
    for (int j = 0; j < 32; j += 8) {
        int l = l0 + ty + j;
        if (l >= LM_) break;
        float r  = sr[tx][ty + j];
        float im = si[tx][ty + j];
        long b0 = ((long)l * 512 + o) * 512 + 2 * c;
        long b1 = ((long)l * 512 + o + 256) * 512 + 2 * c;
        *(__half2*)&g_A2[slot][b0] = __floats2half2_rn(r, -im);
        *(__half2*)&g_A2[slot][b1] = __floats2half2_rn(im, r);
    }
}

// ---------------- casts ----------------
__global__ void k_castw(const float* __restrict__ s, __half* __restrict__ d, int n) {
    int i = blockIdx.x * blockDim.x + threadIdx.x;
    if (i < n) d[i] = __float2half(s[i]);
}
__global__ void k_cast_dec1(const float* __restrict__ s) {
    int i = blockIdx.x * blockDim.x + threadIdx.x;
    if (i >= E_ * 264) return;
    int r = i / 264, c = i % 264;
    g_w_dec1[i] = (c < 258) ? __float2half(s[r * 258 + c]) : __half(0);
}
__global__ void k_castx(const float* __restrict__ x) {
    int i = blockIdx.x * blockDim.x + threadIdx.x;
    if (i < 2 * HW) g_hA_h[E_ * HW + i] = __float2half(x[i]);
}

// encoder stage 1: 2 pixels/thread, half2 stores
__global__ void k_enc1(const float* __restrict__ x, const float* __restrict__ w) {
    int p = (blockIdx.x * blockDim.x + threadIdx.x) * 2;
    if (p >= HW) return;
    float x0a = x[p],      x1a = x[HW + p];
    float x0b = x[p + 1],  x1b = x[HW + p + 1];
    #pragma unroll 4
    for (int e = 0; e < E_; e++) {
        float w0 = w[2 * e], w1 = w[2 * e + 1];
        float va = gelu_f(w0 * x0a + w1 * x1a);
        float vb = gelu_f(w0 * x0b + w1 * x1b);
        *(__half2*)&g_hB_h[e * HW + p] = __floats2half2_rn(va, vb);
    }
}

// ---------------- fp16 tensor-core GEMM, 4-stage cp.async (R6 structure) ----------------
// MODE 0: std epilogue. 1: rfft scatter -> g_xfh. 2: legfwd -> g_cfh.
// 3: spectral -> g_cf2h. 4: leginv -> g_xf2h.
// ADDH: add fp16 ADDh tensor (half2 reads) in MODE 0.
template <int MODE, bool GELU, bool ADDF, bool WF32, bool WF16, bool ADDH = false>
__global__ __launch_bounds__(256, 2) void k_hgemm(
    const __half* __restrict__ A, const __half* __restrict__ B,
    float* __restrict__ C, const float* __restrict__ ADD, __half* __restrict__ Ch,
    const __half* __restrict__ ADDh,
    int M, int N, int K, int lda, long sA, long sB, long sC) {
    extern __shared__ __half dsm[];
    typedef __half (*AsT)[128][40];
    typedef __half (*BsT)[32][136];
    AsT As = (AsT)dsm;
    BsT Bs = (BsT)(dsm + STG * 128 * 40);
    const int tid = threadIdx.x, lane = tid & 31, wid = tid >> 5;
    const int wm = wid >> 2, wn = wid & 3;
    const int bm = blockIdx.y * 128, bn = blockIdx.x * 128;
    const int z = blockIdx.z;
    A += (long)z * sA;
    B += (long)z * sB;
    if (WF32 && MODE == 0) C += (long)z * sC;

    const int r_a = tid >> 1, off_a = (tid & 1) * 16;
    #define LOAD_STAGE(k0, buf)                                                     \
        {                                                                           \
            const __half* pA = A + (long)(bm + r_a) * lda + (k0) + off_a;           \
            bool pa0 = ((k0) + off_a + 8  <= lda);                                  \
            bool pa1 = ((k0) + off_a + 16 <= lda);                                  \
            cp16(&As[buf][r_a][off_a],     pa0 ? pA     : A, pa0);                  \
            cp16(&As[buf][r_a][off_a + 8], pa1 ? pA + 8 : A, pa1);                  \
            _Pragma("unroll")                                                       \
            for (int i = 0; i < 2; i++) {                                           \
                int idx = tid + i * 256;                                            \
                int kk = idx >> 4, noff = (idx & 15) * 8;                           \
                int gk = (k0) + kk, gn = bn + noff;                                 \
                bool pb = (gk < K && gn + 8 <= N);                                  \
                cp16(&Bs[buf][kk][noff], pb ? B + (long)gk * N + gn : B, pb);       \
            }                                                                       \
            asm volatile("cp.async.commit_group;\n" ::);                            \
        }

    float acc[4][4][4];
    #pragma unroll
    for (int i = 0; i < 4; i++)
        #pragma unroll
        for (int j = 0; j < 4; j++)
            #pragma unroll
            for (int q = 0; q < 4; q++) acc[i][j][q] = 0.f;

    LOAD_STAGE(0, 0)
    LOAD_STAGE(32, 1)
    LOAD_STAGE(64, 2)

    const int nslab = (K + 31) / 32;
    for (int it = 0; it < nslab; it++) {
        asm volatile("cp.async.wait_group 2;\n" ::);
        __syncthreads();
        const int buf = it & 3;
        #pragma unroll
        for (int ks = 0; ks < 32; ks += 16) {
            unsigned a[4][4], b[4][2];
            #pragma unroll
            for (int mt = 0; mt < 4; mt++) {
                unsigned addr = smem_u32(&As[buf][wm * 64 + mt * 16 + (lane & 15)][ks + 8 * (lane >> 4)]);
                asm volatile("ldmatrix.sync.aligned.m8n8.x4.shared.b16 {%0,%1,%2,%3},[%4];"
                             : "=r"(a[mt][0]), "=r"(a[mt][1]), "=r"(a[mt][2]), "=r"(a[mt][3])
                             : "r"(addr));
            }
            #pragma unroll
            for (int nt = 0; nt < 4; nt++) {
                unsigned addr = smem_u32(&Bs[buf][ks + (lane & 15)][wn * 32 + nt * 8]);
                asm volatile("ldmatrix.sync.aligned.m8n8.x2.trans.shared.b16 {%0,%1},[%2];"
                             : "=r"(b[nt][0]), "=r"(b[nt][1])
                             : "r"(addr));
            }
            #pragma unroll
            for (int mt = 0; mt < 4; mt++)
                #pragma unroll
                for (int nt = 0; nt < 4; nt++)
                    asm volatile(
                        "mma.sync.aligned.m16n8k16.row.col.f32.f16.f16.f32 "
                        "{%0,%1,%2,%3},{%4,%5,%6,%7},{%8,%9},{%0,%1,%2,%3};"
                        : "+f"(acc[mt][nt][0]), "+f"(acc[mt][nt][1]),
                          "+f"(acc[mt][nt][2]), "+f"(acc[mt][nt][3])
                        : "r"(a[mt][0]), "r"(a[mt][1]), "r"(a[mt][2]), "r"(a[mt][3]),
                          "r"(b[nt][0]), "r"(b[nt][1]));
        }
        __syncthreads();
        int k0n = (it + 3) * 32;
        if (k0n < K) {
            LOAD_STAGE(k0n, (it + 3) & 3)
        } else {
            asm volatile("cp.async.commit_group;\n" ::);
        }
    }
    #undef LOAD_STAGE

    const int g = lane >> 2, tq = lane & 3;
    #pragma unroll
    for (int mt = 0; mt < 4; mt++) {
        #pragma unroll
        for (int hh = 0; hh < 2; hh++) {
            int gm = bm + wm * 64 + mt * 16 + g + hh * 8;
            float vv0, vv1;
            #pragma unroll
            for (int nt = 0; nt < 4; nt++) {
                int gn = bn + wn * 32 + nt * 8 + tq * 2;
                vv0 = acc[mt][nt][hh * 2 + 0];
                vv1 = acc[mt][nt][hh * 2 + 1];
                if (MODE == 1) {
                    if (gn < 2 * MM_) {
                        int m = gn >> 1;
                        int c = gm / H_, y = gm - c * H_;
                        *(__half2*)&g_xfh[(long)m * (H_ * 512) + y * 512 + 2 * c] =
                            __floats2half2_rn(vv0, vv1);
                    }
                } else if (MODE == 2) {
                    if (gm < LM_) {
                        long base = ((long)gm * 512 + gn) * 96 + z;
                        g_cfh[base]      = __float2half(vv0);
                        g_cfh[base + 96] = __float2half(vv1);
                    }
                } else if (MODE == 3) {
                    if (gn < MM_)
                        g_cf2h[((long)gn * 512 + gm) * 96 + z] = __float2half(vv0);
                    if (gn + 1 < MM_)
                        g_cf2h[((long)(gn + 1) * 512 + gm) * 96 + z] = __float2half(vv1);
                } else if (MODE == 4) {
                    int oo = gm & 255, ri = gm >> 8;
                    if (gn < H_) {
                        long addr = ((long)oo * H_ + gn) * 184 + 2 * z + ri;
                        g_xf2h[addr] = __float2half(vv0);
                        if (gn + 1 < H_) g_xf2h[addr + 184] = __float2half(vv1);
                    }
                } else {
                    if (gm >= M || gn >= N) continue;
                    if (GELU) { vv0 = gelu_f(vv0); vv1 = gelu_f(vv1); }
                    if (ADDF) {
                        float2 ad = *(const float2*)&ADD[(long)gm * N + gn];
                        vv0 += ad.x; vv1 += ad.y;
                    }
                    if (ADDH) {
                        __half2 ah = *(const __half2*)&ADDh[(long)gm * N + gn];
                        float2 af = __half22float2(ah);
                        vv0 += af.x; vv1 += af.y;
                    }
                    if (WF32) *(float2*)&C[(long)gm * N + gn] = make_float2(vv0, vv1);
                    if (WF16) *(__half2*)&Ch[(long)gm * N + gn] = __floats2half2_rn(vv0, vv1);
                }
            }
        }
    }
}

// decoder stage 2: 2 pixels/thread, half2 loads
__global__ void k_dec2(const float* __restrict__ w, float* __restrict__ out) {
    int p = (blockIdx.x * blockDim.x + threadIdx.x) * 2;
    if (p >= HW) return;
    float a0 = 0.f, a1 = 0.f, b0 = 0.f, b1 = 0.f;
    #pragma unroll 4
    for (int c = 0; c < E_; c++) {
        __half2 vh = *(const __half2*)&g_t_h[c * HW + p];
        float2 vf = __half22float2(vh);
        float w0 = w[c], w1 = w[E_ + c];
        a0 += w0 * vf.x; b0 += w0 * vf.y;
        a1 += w1 * vf.x; b1 += w1 * vf.y;
    }
    out[p] = a0;       out[p + 1] = b0;
    out[HW + p] = a1;  out[HW + p + 1] = b1;
}

extern "C" void kernel_launch(void* const* d_in, const int* in_sizes, int n_in,
                              void* d_out, int out_size) {
    const float* x        = (const float*)d_in[0];
    const float* enc_w1   = (const float*)d_in[1];
    const float* enc_w2   = (const float*)d_in[2];
    const float* pos      = (const float*)d_in[3];
    const float* leg_fwd  = (const float*)d_in[4];
    const float* leg_inv  = (const float*)d_in[5];
    const float* w_spec_r = (const float*)d_in[6];
    const float* w_spec_i = (const float*)d_in[7];
    const float* w_inner  = (const float*)d_in[8];
    const float* w_mlp1   = (const float*)d_in[9];
    const float* w_mlp2   = (const float*)d_in[10];
    const float* dec_w1   = (const float*)d_in[11];
    const float* dec_w2   = (const float*)d_in[12];
    float* out = (float*)d_out;

    float* hA;
    __half *Ph, *hAh, *hBh, *tH, *wEnc2, *wInn, *wM1, *wM2, *wDec1;
    __half *Fh, *Gih, *xfh, *cfh, *cf2h, *xf2h, *legfH, *legiH, *A2;
    cudaGetSymbolAddress((void**)&hA, g_hA);
    cudaGetSymbolAddress((void**)&Ph, g_P_h);
    cudaGetSymbolAddress((void**)&hAh, g_hA_h);
    cudaGetSymbolAddress((void**)&hBh, g_hB_h);
    cudaGetSymbolAddress((void**)&tH, g_t_h);
    cudaGetSymbolAddress((void**)&wEnc2, g_w_enc2);
    cudaGetSymbolAddress((void**)&wInn, g_w_inner);
    cudaGetSymbolAddress((void**)&wM1, g_w_mlp1);
    cudaGetSymbolAddress((void**)&wM2, g_w_mlp2);
    cudaGetSymbolAddress((void**)&wDec1, g_w_dec1);
    cudaGetSymbolAddress((void**)&Fh, g_F_h);
    cudaGetSymbolAddress((void**)&Gih, g_Gi_h);
    cudaGetSymbolAddress((void**)&xfh, g_xfh);
    cudaGetSymbolAddress((void**)&cfh, g_cfh);
    cudaGetSymbolAddress((void**)&cf2h, g_cf2h);
    cudaGetSymbolAddress((void**)&xf2h, g_xf2h);
    cudaGetSymbolAddress((void**)&legfH, g_legf_h);
    cudaGetSymbolAddress((void**)&legiH, g_legi_h);
    cudaGetSymbolAddress((void**)&A2, g_A2);

    cudaFuncSetAttribute(k_hgemm<0, false, true,  true,  true >, cudaFuncAttributeMaxDynamicSharedMemorySize, SMEMSZ);
    cudaFuncSetAttribute(k_hgemm<0, false, true,  false, true >, cudaFuncAttributeMaxDynamicSharedMemorySize, SMEMSZ);
    cudaFuncSetAttribute(k_hgemm<0, true,  false, false, true >, cudaFuncAttributeMaxDynamicSharedMemorySize, SMEMSZ);
    cudaFuncSetAttribute(k_hgemm<0, false, false, false, true >, cudaFuncAttributeMaxDynamicSharedMemorySize, SMEMSZ);
    cudaFuncSetAttribute(k_hgemm<0, false, false, false, true, true>, cudaFuncAttributeMaxDynamicSharedMemorySize, SMEMSZ);
    cudaFuncSetAttribute(k_hgemm<1, false, false, false, false>, cudaFuncAttributeMaxDynamicSharedMemorySize, SMEMSZ);
    cudaFuncSetAttribute(k_hgemm<2, false, false, false, false>, cudaFuncAttributeMaxDynamicSharedMemorySize, SMEMSZ);
    cudaFuncSetAttribute(k_hgemm<3, false, false, false, false>, cudaFuncAttributeMaxDynamicSharedMemorySize, SMEMSZ);
    cudaFuncSetAttribute(k_hgemm<4, false, false, false, false>, cudaFuncAttributeMaxDynamicSharedMemorySize, SMEMSZ);

    static cudaStream_t s1 = nullptr, s2 = nullptr;
    static cudaEvent_t evRoot, evInit, evW, evA2[NLAY], evL[NLAY], evP[NLAY];
    if (!s1) {
        cudaStreamCreateWithFlags(&s1, cudaStreamNonBlocking);
        cudaStreamCreateWithFlags(&s2, cudaStreamNonBlocking);
        cudaEventCreateWithFlags(&evRoot, cudaEventDisableTiming);
        cudaEventCreateWithFlags(&evInit, cudaEventDisableTiming);
        cudaEventCreateWithFlags(&evW, cudaEventDisableTiming);
        for (int i = 0; i < NLAY; i++) {
            cudaEventCreateWithFlags(&evA2[i], cudaEventDisableTiming);
            cudaEventCreateWithFlags(&evL[i], cudaEventDisableTiming);
            cudaEventCreateWithFlags(&evP[i], cudaEventDisableTiming);
        }
    }

    const int NB = (HW + 127) / 128;   // 507
    dim3 gE(NB, E_ / 128);
    dim3 gH(NB, HID_ / 128);
    dim3 gRF(2, 360);
    dim3 gLF(4, 1, MM_);
    dim3 gSP(1, 4, LM_);
    dim3 gLI(2, 4, MM_);
    dim3 gIR(3, 360);
    dim3 gB2(8, 3, 256), bB2(32, 8);

    // ---- fork init stream ----
    cudaEventRecord(evRoot, 0);
    cudaStreamWaitEvent(s1, evRoot, 0);
    k_castw<<<(E_ * E_ + 255) / 256, 256, 0, s1>>>(enc_w2, wEnc2, E_ * E_);
    cudaEventRecord(evW, s1);
    k_castw<<<(NLAY * E_ * E_ + 255) / 256, 256, 0, s1>>>(w_inner, wInn, NLAY * E_ * E_);
    k_castw<<<(NLAY * HID_ * E_ + 255) / 256, 256, 0, s1>>>(w_mlp1, wM1, NLAY * HID_ * E_);
    k_castw<<<(NLAY * E_ * HID_ + 255) / 256, 256, 0, s1>>>(w_mlp2, wM2, NLAY * E_ * HID_);
    k_init_tables<<<(W_ * 184 + 255) / 256, 256, 0, s1>>>();
    k_zero_cfh<<<(LM_ * 512 * 96 / 8 + 255) / 256, 256, 0, s1>>>();
    k_cast_leg<<<(MM_ * LM_ * 184 + 255) / 256, 256, 0, s1>>>(leg_fwd, legfH);
    k_cast_leg<<<(MM_ * LM_ * 184 + 255) / 256, 256, 0, s1>>>(leg_inv, legiH);
    k_cast_dec1<<<(E_ * 264 + 255) / 256, 256, 0, s1>>>(dec_w1);
    k_castx<<<(2 * HW + 255) / 256, 256, 0, s1>>>(x);
    cudaEventRecord(evInit, s1);
    for (int i = 0; i < NLAY; i++) {
        k_buildA2_t<<<gB2, bB2, 0, s1>>>(w_spec_r + (long)i * E_ * E_ * LM_,
                                         w_spec_i + (long)i * E_ * E_ * LM_, i);
        cudaEventRecord(evA2[i], s1);
    }

    // ---- main: encoder ----
    k_enc1<<<(HW / 2 + 255) / 256, 256>>>(x, enc_w1);
    cudaStreamWaitEvent(0, evW, 0);
    k_hgemm<0, false, true, true, true><<<gE, 256, SMEMSZ>>>(wEnc2, hBh, hA, pos, hAh,
                                                             nullptr, E_, HW, E_, E_, 0, 0, 0);
    cudaEventRecord(evL[0], 0);
    cudaStreamWaitEvent(0, evInit, 0);

    for (int i = 0; i < NLAY; i++) {
        // side s2: Ph = fp16( w_inner[i] @ hAh ), concurrent with spectral chain
        cudaStreamWaitEvent(s2, evL[i], 0);
        if (i == 0) cudaStreamWaitEvent(s2, evInit, 0);
        k_hgemm<0, false, false, false, true><<<gE, 256, SMEMSZ, s2>>>(
            wInn + (long)i * E_ * E_, hAh, nullptr, nullptr, Ph, nullptr,
            E_, HW, E_, E_, 0, 0, 0);
        cudaEventRecord(evP[i], s2);

        // main: spectral chain
        k_hgemm<1, false, false, false, false><<<gRF, 256, SMEMSZ>>>(
            hAh, Fh, nullptr, nullptr, nullptr, nullptr, 46080, 184, W_, W_, 0, 0, 0);
        k_hgemm<2, false, false, false, false><<<gLF, 256, SMEMSZ>>>(
            legfH, xfh, nullptr, nullptr, nullptr, nullptr, LM_, 512, H_, 184,
            (long)LM_ * 184, (long)H_ * 512, 0);
        cudaStreamWaitEvent(0, evA2[i], 0);
        k_hgemm<3, false, false, false, false><<<gSP, 256, SMEMSZ>>>(
            A2 + (long)i * LM_ * 512 * 512, cfh, nullptr, nullptr, nullptr, nullptr,
            512, 96, 512, 512, (long)512 * 512, (long)512 * 96, 0);
        k_hgemm<4, false, false, false, false><<<gLI, 256, SMEMSZ>>>(
            cf2h, legiH, nullptr, nullptr, nullptr, nullptr, 512, 184, LM_, 96,
            (long)512 * 96, (long)LM_ * 184, 0);
        // irfft + inner skip fused: hBh = fp16( irfft(xf2h) + Ph )
        cudaStreamWaitEvent(0, evP[i], 0);
        k_hgemm<0, false, false, false, true, true><<<gIR, 256, SMEMSZ>>>(
            xf2h, Gih, nullptr, nullptr, hBh, Ph, 46080, W_, 182, 184, 0, 0, 0);
        // t_h = fp16( gelu(w_mlp1 @ hBh) )
        k_hgemm<0, true, false, false, true><<<gH, 256, SMEMSZ>>>(
            wM1 + (long)i * HID_ * E_, hBh, nullptr, nullptr, tH, nullptr,
            HID_, HW, E_, E_, 0, 0, 0);
        // hA(+hAh) = w_mlp2 @ t_h + hA  (last layer: fp16 only)
        if (i + 1 < NLAY)
            k_hgemm<0, false, true, true, true><<<gE, 256, SMEMSZ>>>(
                wM2 + (long)i * E_ * HID_, tH, hA, hA, hAh, nullptr,
                E_, HW, HID_, HID_, 0, 0, 0);
        else
            k_hgemm<0, false, true, false, true><<<gE, 256, SMEMSZ>>>(
                wM2 + (long)i * E_ * HID_, tH, nullptr, hA, hAh, nullptr,
                E_, HW, HID_, HID_, 0, 0, 0);
        if (i + 1 < NLAY) cudaEventRecord(evL[i + 1], 0);
    }

    k_hgemm<0, true, false, false, true><<<gE, 256, SMEMSZ>>>(wDec1, hAh, nullptr, nullptr,
                                                              tH, nullptr, E_, HW, 258, 264, 0, 0, 0);
    k_dec2<<<(HW / 2 + 255) / 256, 256>>>(dec_w2, out);
}

// round 12
// speedup vs baseline: 1.0899x; 1.0485x over previous
#include <cuda_runtime.h>
#include <cuda_fp16.h>
#include <math.h>

#define HW   64800
#define E_   256
#define NLAY 4
#define LM_  90
#define MM_  91
#define HID_ 512
#define H_   180
#define W_   360
#define STG  4
#define SMEMSZ (STG * (128 * 40 + 32 * 136) * 2)

// ---------------- scratch (device globals) ----------------
__device__ float  g_hA[E_ * HW];           // fp32 h (residual)
__device__ __half g_P_h[E_ * HW];          // fp16 inner-skip product (side stream)
__device__ __half g_hA_h[(E_ + 2) * HW];   // fp16 h; rows 256,257 = raw x
__device__ __half g_hB_h[E_ * HW];
__device__ __half g_t_h [HID_ * HW];
__device__ __half g_xfh [MM_ * 512 * 184]; // rfft out: [m][2c+ri][y pad184]
__device__ __half g_cfh [LM_ * 512 * 96];  // legfwd out: [l][2c+ri][m] (m pad 96)
__device__ __half g_cf2h[MM_ * 512 * 96];  // spectral out: [m][o2][l] (l pad 96)
__device__ __half g_xf2h[46080 * 184];     // leginv out: [(o,y)][2m+ri] (pad 184)
__device__ __half g_F_h [W_ * 184];        // rfft DFT [x][2m+ri]
__device__ __half g_Gi_h[182 * W_];        // irfft DFT [2m+ri][x]
__device__ __half g_legfT_h[MM_ * 184 * 96];            // fwd Legendre, [m][y pad184][l pad96]
__device__ __half g_legi_h[MM_ * LM_ * 184];            // inv Legendre, [m][l][h pad184]
__device__ __half g_A2[NLAY][LM_ * 512 * 512];  // spectral fp16 weights, all layers
// fp16 weights
__device__ __half g_w_enc2[E_ * E_];
__device__ __half g_w_inner[NLAY * E_ * E_];
__device__ __half g_w_mlp1[NLAY * HID_ * E_];
__device__ __half g_w_mlp2[NLAY * E_ * HID_];
__device__ __half g_w_dec1[E_ * 264];

__device__ __forceinline__ float gelu_f(float v) {
    return 0.5f * v * (1.0f + erff(v * 0.7071067811865475f));
}
__device__ __forceinline__ unsigned smem_u32(const void* p) {
    return (unsigned)__cvta_generic_to_shared(p);
}
__device__ __forceinline__ void cp16(void* s, const void* g, bool p) {
    unsigned sa = smem_u32(s);
    asm volatile("cp.async.cg.shared.global [%0],[%1],16,%2;\n"
                 :: "r"(sa), "l"(g), "r"(p ? 16 : 0));
}

// ---------------- DFT tables ----------------
__global__ void k_init_tables() {
    int idx = blockIdx.x * blockDim.x + threadIdx.x;
    if (idx < W_ * 184) {
        int x = idx / 184, col = idx % 184;
        float v = 0.f;
        if (col < 182) {
            int m = col >> 1, ri = col & 1;
            int r = (m * x) % W_;
            double s, c;
            sincospi((double)r / 180.0, &s, &c);
            v = ri ? (float)(-s) : (float)c;
        }
        g_F_h[idx] = __float2half(v);
    }
    if (idx < 182 * W_) {
        int k = idx / W_, x = idx % W_;
        int m = k >> 1, ri = k & 1;
        int r = (m * x) % W_;
        double s, c;
        sincospi((double)r / 180.0, &s, &c);
        double sc = (m == 0) ? (1.0 / 360.0) : (2.0 / 360.0);
        g_Gi_h[idx] = __float2half(ri ? (float)(-sc * s) : (float)(sc * c));
    }
}

__global__ void k_zero_cfh() {
    int i = blockIdx.x * blockDim.x + threadIdx.x;
    if (i < LM_ * 512 * 96 / 8) ((uint4*)g_cfh)[i] = make_uint4(0, 0, 0, 0);
}

// fwd Legendre transposed: legfT[m][y][l] = legf[m][l][y], zero-padded (y->184, l->96)
__global__ void k_cast_legfT(const float* __restrict__ s) {
    int i = blockIdx.x * blockDim.x + threadIdx.x;
    if (i >= MM_ * 184 * 96) return;
    int l = i % 96, y = (i / 96) % 184, m = i / (96 * 184);
    float v = (l < LM_ && y < H_) ? s[((long)m * LM_ + l) * H_ + y] : 0.f;
    g_legfT_h[i] = __float2half(v);
}

// inv Legendre: [m][l][h<180] -> fp16 [m][l][184], pad 0
__global__ void k_cast_leg(const float* __restrict__ s, __half* __restrict__ d) {
    int i = blockIdx.x * blockDim.x + threadIdx.x;
    if (i >= MM_ * LM_ * 184) return;
    int col = i % 184, row = i / 184;
    d[i] = (col < H_) ? __float2half(s[row * H_ + col]) : __half(0);
}

// transpose-tiled spectral weight build
__global__ void k_buildA2_t(const float* __restrict__ wr, const float* __restrict__ wi, int slot) {
    int o  = blockIdx.z;
    int c0 = blockIdx.x * 32;
    int l0 = blockIdx.y * 32;
    __shared__ float sr[32][33], si[32][33];
    int tx = threadIdx.x, ty = threadIdx.y;
    #pragma unroll
    for (int i = 0; i < 32; i += 8) {
        int c = c0 + ty + i, l = l0 + tx;
        long base = ((long)o * E_ + c) * LM_ + l;
        bool ok = (l < LM_);
        sr[ty + i][tx] = ok ? wr[base] : 0.f;
        si[ty + i][tx] = ok ? wi[base] : 0.f;
    }
    __syncthreads();
    int c = c0 + tx;
    #pragma unroll
    for (int j = 0; j < 32; j += 8) {
        int l = l0 + ty + j;
        if (l >= LM_) break;
        float r  = sr[tx][ty + j];
        float im = si[tx][ty + j];
        long b0 = ((long)l * 512 + o) * 512 + 2 * c;
        long b1 = ((long)l * 512 + o + 256) * 512 + 2 * c;
        *(__half2*)&g_A2[slot][b0] = __floats2half2_rn(r, -im);
        *(__half2*)&g_A2[slot][b1] = __floats2half2_rn(im, r);
    }
}

// ---------------- casts ----------------
__global__ void k_castw(const float* __restrict__ s, __half* __restrict__ d, int n) {
    int i = blockIdx.x * blockDim.x + threadIdx.x;
    if (i < n) d[i] = __float2half(s[i]);
}
__global__ void k_cast_dec1(const float* __restrict__ s) {
    int i = blockIdx.x * blockDim.x + threadIdx.x;
    if (i >= E_ * 264) return;
    int r = i / 264, c = i % 264;
    g_w_dec1[i] = (c < 258) ? __float2half(s[r * 258 + c]) : __half(0);
}
__global__ void k_castx(const float* __restrict__ x) {
    int i = blockIdx.x * blockDim.x + threadIdx.x;
    if (i < 2 * HW) g_hA_h[E_ * HW + i] = __float2half(x[i]);
}

// encoder stage 1: 2 pixels/thread, half2 stores
__global__ void k_enc1(const float* __restrict__ x, const float* __restrict__ w) {
    int p = (blockIdx.x * blockDim.x + threadIdx.x) * 2;
    if (p >= HW) return;
    float x0a = x[p],      x1a = x[HW + p];
    float x0b = x[p + 1],  x1b = x[HW + p + 1];
    #pragma unroll 4
    for (int e = 0; e < E_; e++) {
        float w0 = w[2 * e], w1 = w[2 * e + 1];
        float va = gelu_f(w0 * x0a + w1 * x1a);
        float vb = gelu_f(w0 * x0b + w1 * x1b);
        *(__half2*)&g_hB_h[e * HW + p] = __floats2half2_rn(va, vb);
    }
}

// ---------------- fp16 tensor-core GEMM, 4-stage cp.async (R6 structure) ----------------
// MODE 0: std epilogue. 1: rfft -> g_xfh [m][c2][y] (coalesced). 2: legfwd -> g_cfh.
// 3: spectral -> g_cf2h. 4: leginv -> g_xf2h.
// ADDH: add fp16 ADDh tensor (half2 reads) in MODE 0.
template <int MODE, bool GELU, bool ADDF, bool WF32, bool WF16, bool ADDH = false>
__global__ __launch_bounds__(256, 2) void k_hgemm(
    const __half* __restrict__ A, const __half* __restrict__ B,
    float* __restrict__ C, const float* __restrict__ ADD, __half* __restrict__ Ch,
    const __half* __restrict__ ADDh,
    int M, int N, int K, int lda, long sA, long sB, long sC) {
    extern __shared__ __half dsm[];
    typedef __half (*AsT)[128][40];
    typedef __half (*BsT)[32][136];
    AsT As = (AsT)dsm;
    BsT Bs = (BsT)(dsm + STG * 128 * 40);
    const int tid = threadIdx.x, lane = tid & 31, wid = tid >> 5;
    const int wm = wid >> 2, wn = wid & 3;
    const int bm = blockIdx.y * 128, bn = blockIdx.x * 128;
    const int z = blockIdx.z;
    A += (long)z * sA;
    B += (long)z * sB;
    if (WF32 && MODE == 0) C += (long)z * sC;

    const int r_a = tid >> 1, off_a = (tid & 1) * 16;
    #define LOAD_STAGE(k0, buf)                                                     \
        {                                                                           \
            const __half* pA = A + (long)(bm + r_a) * lda + (k0) + off_a;           \
            bool pa0 = ((k0) + off_a + 8  <= lda);                                  \
            bool pa1 = ((k0) + off_a + 16 <= lda);                                  \
            cp16(&As[buf][r_a][off_a],     pa0 ? pA     : A, pa0);                  \
            cp16(&As[buf][r_a][off_a + 8], pa1 ? pA + 8 : A, pa1);                  \
            _Pragma("unroll")                                                       \
            for (int i = 0; i < 2; i++) {                                           \
                int idx = tid + i * 256;                                            \
                int kk = idx >> 4, noff = (idx & 15) * 8;                           \
                int gk = (k0) + kk, gn = bn + noff;                                 \
                bool pb = (gk < K && gn + 8 <= N);                                  \
                cp16(&Bs[buf][kk][noff], pb ? B + (long)gk * N + gn : B, pb);       \
            }                                                                       \
            asm volatile("cp.async.commit_group;\n" ::);                            \
        }

    float acc[4][4][4];
    #pragma unroll
    for (int i = 0; i < 4; i++)
        #pragma unroll
        for (int j = 0; j < 4; j++)
            #pragma unroll
            for (int q = 0; q < 4; q++) acc[i][j][q] = 0.f;

    LOAD_STAGE(0, 0)
    LOAD_STAGE(32, 1)
    LOAD_STAGE(64, 2)

    const int nslab = (K + 31) / 32;
    for (int it = 0; it < nslab; it++) {
        asm volatile("cp.async.wait_group 2;\n" ::);
        __syncthreads();
        const int buf = it & 3;
        #pragma unroll
        for (int ks = 0; ks < 32; ks += 16) {
            unsigned a[4][4], b[4][2];
            #pragma unroll
            for (int mt = 0; mt < 4; mt++) {
                unsigned addr = smem_u32(&As[buf][wm * 64 + mt * 16 + (lane & 15)][ks + 8 * (lane >> 4)]);
                asm volatile("ldmatrix.sync.aligned.m8n8.x4.shared.b16 {%0,%1,%2,%3},[%4];"
                             : "=r"(a[mt][0]), "=r"(a[mt][1]), "=r"(a[mt][2]), "=r"(a[mt][3])
                             : "r"(addr));
            }
            #pragma unroll
            for (int nt = 0; nt < 4; nt++) {
                unsigned addr = smem_u32(&Bs[buf][ks + (lane & 15)][wn * 32 + nt * 8]);
                asm volatile("ldmatrix.sync.aligned.m8n8.x2.trans.shared.b16 {%0,%1},[%2];"
                             : "=r"(b[nt][0]), "=r"(b[nt][1])
                             : "r"(addr));
            }
            #pragma unroll
            for (int mt = 0; mt < 4; mt++)
                #pragma unroll
                for (int nt = 0; nt < 4; nt++)
                    asm volatile(
                        "mma.sync.aligned.m16n8k16.row.col.f32.f16.f16.f32 "
                        "{%0,%1,%2,%3},{%4,%5,%6,%7},{%8,%9},{%0,%1,%2,%3};"
                        : "+f"(acc[mt][nt][0]), "+f"(acc[mt][nt][1]),
                          "+f"(acc[mt][nt][2]), "+f"(acc[mt][nt][3])
                        : "r"(a[mt][0]), "r"(a[mt][1]), "r"(a[mt][2]), "r"(a[mt][3]),
                          "r"(b[nt][0]), "r"(b[nt][1]));
        }
        __syncthreads();
        int k0n = (it + 3) * 32;
        if (k0n < K) {
            LOAD_STAGE(k0n, (it + 3) & 3)
        } else {
            asm volatile("cp.async.commit_group;\n" ::);
        }
    }
    #undef LOAD_STAGE

    const int g = lane >> 2, tq = lane & 3;
    #pragma unroll
    for (int mt = 0; mt < 4; mt++) {
        #pragma unroll
        for (int hh = 0; hh < 2; hh++) {
            int gm = bm + wm * 64 + mt * 16 + g + hh * 8;
            float vv0, vv1;
            #pragma unroll
            for (int nt = 0; nt < 4; nt++) {
                int gn = bn + wn * 32 + nt * 8 + tq * 2;
                vv0 = acc[mt][nt][hh * 2 + 0];
                vv1 = acc[mt][nt][hh * 2 + 1];
                if (MODE == 1) {
                    // gn = 2m+ri (even), gm = c*H + y. write [m][2c][y] and [m][2c+1][y]
                    if (gn < 2 * MM_) {
                        int m = gn >> 1;
                        int c = gm / H_, y = gm - c * H_;
                        long base = (long)m * (512 * 184) + (2 * c) * 184 + y;
                        g_xfh[base]       = __float2half(vv0);  // re
                        g_xfh[base + 184] = __float2half(vv1);  // im
                    }
                } else if (MODE == 2) {
                    // gm = c2, gn = l, z = m -> cfh[l][c2][m]
                    if (gn < LM_)
                        g_cfh[((long)gn * 512 + gm) * 96 + z] = __float2half(vv0);
                    if (gn + 1 < LM_)
                        g_cfh[((long)(gn + 1) * 512 + gm) * 96 + z] = __float2half(vv1);
                } else if (MODE == 3) {
                    if (gn < MM_)
                        g_cf2h[((long)gn * 512 + gm) * 96 + z] = __float2half(vv0);
                    if (gn + 1 < MM_)
                        g_cf2h[((long)(gn + 1) * 512 + gm) * 96 + z] = __float2half(vv1);
                } else if (MODE == 4) {
                    int oo = gm & 255, ri = gm >> 8;
                    if (gn < H_) {
                        long addr = ((long)oo * H_ + gn) * 184 + 2 * z + ri;
                        g_xf2h[addr] = __float2half(vv0);
                        if (gn + 1 < H_) g_xf2h[addr + 184] = __float2half(vv1);
                    }
                } else {
                    if (gm >= M || gn >= N) continue;
                    if (GELU) { vv0 = gelu_f(vv0); vv1 = gelu_f(vv1); }
                    if (ADDF) {
                        float2 ad = *(const float2*)&ADD[(long)gm * N + gn];
                        vv0 += ad.x; vv1 += ad.y;
                    }
                    if (ADDH) {
                        __half2 ah = *(const __half2*)&ADDh[(long)gm * N + gn];
                        float2 af = __half22float2(ah);
                        vv0 += af.x; vv1 += af.y;
                    }
                    if (WF32) *(float2*)&C[(long)gm * N + gn] = make_float2(vv0, vv1);
                    if (WF16) *(__half2*)&Ch[(long)gm * N + gn] = __floats2half2_rn(vv0, vv1);
                }
            }
        }
    }
}

// decoder stage 2: 2 pixels/thread, half2 loads
__global__ void k_dec2(const float* __restrict__ w, float* __restrict__ out) {
    int p = (blockIdx.x * blockDim.x + threadIdx.x) * 2;
    if (p >= HW) return;
    float a0 = 0.f, a1 = 0.f, b0 = 0.f, b1 = 0.f;
    #pragma unroll 4
    for (int c = 0; c < E_; c++) {
        __half2 vh = *(const __half2*)&g_t_h[c * HW + p];
        float2 vf = __half22float2(vh);
        float w0 = w[c], w1 = w[E_ + c];
        a0 += w0 * vf.x; b0 += w0 * vf.y;
        a1 += w1 * vf.x; b1 += w1 * vf.y;
    }
    out[p] = a0;       out[p + 1] = b0;
    out[HW + p] = a1;  out[HW + p + 1] = b1;
}

extern "C" void kernel_launch(void* const* d_in, const int* in_sizes, int n_in,
                              void* d_out, int out_size) {
    const float* x        = (const float*)d_in[0];
    const float* enc_w1   = (const float*)d_in[1];
    const float* enc_w2   = (const float*)d_in[2];
    const float* pos      = (const float*)d_in[3];
    const float* leg_fwd  = (const float*)d_in[4];
    const float* leg_inv  = (const float*)d_in[5];
    const float* w_spec_r = (const float*)d_in[6];
    const float* w_spec_i = (const float*)d_in[7];
    const float* w_inner  = (const float*)d_in[8];
    const float* w_mlp1   = (const float*)d_in[9];
    const float* w_mlp2   = (const float*)d_in[10];
    const float* dec_w1   = (const float*)d_in[11];
    const float* dec_w2   = (const float*)d_in[12];
    float* out = (float*)d_out;

    float* hA;
    __half *Ph, *hAh, *hBh, *tH, *wEnc2, *wInn, *wM1, *wM2, *wDec1;
    __half *Fh, *Gih, *xfh, *cfh, *cf2h, *xf2h, *legfT, *legiH, *A2;
    cudaGetSymbolAddress((void**)&hA, g_hA);
    cudaGetSymbolAddress((void**)&Ph, g_P_h);
    cudaGetSymbolAddress((void**)&hAh, g_hA_h);
    cudaGetSymbolAddress((void**)&hBh, g_hB_h);
    cudaGetSymbolAddress((void**)&tH, g_t_h);
    cudaGetSymbolAddress((void**)&wEnc2, g_w_enc2);
    cudaGetSymbolAddress((void**)&wInn, g_w_inner);
    cudaGetSymbolAddress((void**)&wM1, g_w_mlp1);
    cudaGetSymbolAddress((void**)&wM2, g_w_mlp2);
    cudaGetSymbolAddress((void**)&wDec1, g_w_dec1);
    cudaGetSymbolAddress((void**)&Fh, g_F_h);
    cudaGetSymbolAddress((void**)&Gih, g_Gi_h);
    cudaGetSymbolAddress((void**)&xfh, g_xfh);
    cudaGetSymbolAddress((void**)&cfh, g_cfh);
    cudaGetSymbolAddress((void**)&cf2h, g_cf2h);
    cudaGetSymbolAddress((void**)&xf2h, g_xf2h);
    cudaGetSymbolAddress((void**)&legfT, g_legfT_h);
    cudaGetSymbolAddress((void**)&legiH, g_legi_h);
    cudaGetSymbolAddress((void**)&A2, g_A2);

    cudaFuncSetAttribute(k_hgemm<0, false, true,  true,  true >, cudaFuncAttributeMaxDynamicSharedMemorySize, SMEMSZ);
    cudaFuncSetAttribute(k_hgemm<0, false, true,  false, true >, cudaFuncAttributeMaxDynamicSharedMemorySize, SMEMSZ);
    cudaFuncSetAttribute(k_hgemm<0, true,  false, false, true >, cudaFuncAttributeMaxDynamicSharedMemorySize, SMEMSZ);
    cudaFuncSetAttribute(k_hgemm<0, false, false, false, true >, cudaFuncAttributeMaxDynamicSharedMemorySize, SMEMSZ);
    cudaFuncSetAttribute(k_hgemm<0, false, false, false, true, true>, cudaFuncAttributeMaxDynamicSharedMemorySize, SMEMSZ);
    cudaFuncSetAttribute(k_hgemm<1, false, false, false, false>, cudaFuncAttributeMaxDynamicSharedMemorySize, SMEMSZ);
    cudaFuncSetAttribute(k_hgemm<2, false, false, false, false>, cudaFuncAttributeMaxDynamicSharedMemorySize, SMEMSZ);
    cudaFuncSetAttribute(k_hgemm<3, false, false, false, false>, cudaFuncAttributeMaxDynamicSharedMemorySize, SMEMSZ);
    cudaFuncSetAttribute(k_hgemm<4, false, false, false, false>, cudaFuncAttributeMaxDynamicSharedMemorySize, SMEMSZ);

    static cudaStream_t s1 = nullptr, s2 = nullptr;
    static cudaEvent_t evRoot, evInit, evW, evA2[NLAY], evL[NLAY], evP[NLAY];
    if (!s1) {
        cudaStreamCreateWithFlags(&s1, cudaStreamNonBlocking);
        cudaStreamCreateWithFlags(&s2, cudaStreamNonBlocking);
        cudaEventCreateWithFlags(&evRoot, cudaEventDisableTiming);
        cudaEventCreateWithFlags(&evInit, cudaEventDisableTiming);
        cudaEventCreateWithFlags(&evW, cudaEventDisableTiming);
        for (int i = 0; i < NLAY; i++) {
            cudaEventCreateWithFlags(&evA2[i], cudaEventDisableTiming);
            cudaEventCreateWithFlags(&evL[i], cudaEventDisableTiming);
            cudaEventCreateWithFlags(&evP[i], cudaEventDisableTiming);
        }
    }

    const int NB = (HW + 127) / 128;   // 507
    dim3 gE(NB, E_ / 128);
    dim3 gH(NB, HID_ / 128);
    dim3 gRF(2, 360);                  // rfft:   M=46080, N=184
    dim3 gLF(1, 4, MM_);               // legfwd: M=512, N=96, batch m
    dim3 gSP(1, 4, LM_);               // spectral: M=512, N=96, batch l
    dim3 gLI(2, 4, MM_);               // leginv: M=512, N=184, batch m
    dim3 gIR(3, 360);                  // irfft:  M=46080, N=360
    dim3 gB2(8, 3, 256), bB2(32, 8);

    // ---- fork init stream ----
    cudaEventRecord(evRoot, 0);
    cudaStreamWaitEvent(s1, evRoot, 0);
    k_castw<<<(E_ * E_ + 255) / 256, 256, 0, s1>>>(enc_w2, wEnc2, E_ * E_);
    cudaEventRecord(evW, s1);
    k_castw<<<(NLAY * E_ * E_ + 255) / 256, 256, 0, s1>>>(w_inner, wInn, NLAY * E_ * E_);
    k_castw<<<(NLAY * HID_ * E_ + 255) / 256, 256, 0, s1>>>(w_mlp1, wM1, NLAY * HID_ * E_);
    k_castw<<<(NLAY * E_ * HID_ + 255) / 256, 256, 0, s1>>>(w_mlp2, wM2, NLAY * E_ * HID_);
    k_init_tables<<<(W_ * 184 + 255) / 256, 256, 0, s1>>>();
    k_zero_cfh<<<(LM_ * 512 * 96 / 8 + 255) / 256, 256, 0, s1>>>();
    k_cast_legfT<<<(MM_ * 184 * 96 + 255) / 256, 256, 0, s1>>>(leg_fwd);
    k_cast_leg<<<(MM_ * LM_ * 184 + 255) / 256, 256, 0, s1>>>(leg_inv, legiH);
    k_cast_dec1<<<(E_ * 264 + 255) / 256, 256, 0, s1>>>(dec_w1);
    k_castx<<<(2 * HW + 255) / 256, 256, 0, s1>>>(x);
    cudaEventRecord(evInit, s1);
    for (int i = 0; i < NLAY; i++) {
        k_buildA2_t<<<gB2, bB2, 0, s1>>>(w_spec_r + (long)i * E_ * E_ * LM_,
                                         w_spec_i + (long)i * E_ * E_ * LM_, i);
        cudaEventRecord(evA2[i], s1);
    }

    // ---- main: encoder ----
    k_enc1<<<(HW / 2 + 255) / 256, 256>>>(x, enc_w1);
    cudaStreamWaitEvent(0, evW, 0);
    k_hgemm<0, false, true, true, true><<<gE, 256, SMEMSZ>>>(wEnc2, hBh, hA, pos, hAh,
                                                             nullptr, E_, HW, E_, E_, 0, 0, 0);
    cudaEventRecord(evL[0], 0);
    cudaStreamWaitEvent(0, evInit, 0);

    for (int i = 0; i < NLAY; i++) {
        // side s2: Ph = fp16( w_inner[i] @ hAh ), concurrent with spectral chain
        cudaStreamWaitEvent(s2, evL[i], 0);
        if (i == 0) cudaStreamWaitEvent(s2, evInit, 0);
        k_hgemm<0, false, false, false, true><<<gE, 256, SMEMSZ, s2>>>(
            wInn + (long)i * E_ * E_, hAh, nullptr, nullptr, Ph, nullptr,
            E_, HW, E_, E_, 0, 0, 0);
        cudaEventRecord(evP[i], s2);

        // main: spectral chain
        // rfft -> xfh[m][c2][y]
        k_hgemm<1, false, false, false, false><<<gRF, 256, SMEMSZ>>>(
            hAh, Fh, nullptr, nullptr, nullptr, nullptr, 46080, 184, W_, W_, 0, 0, 0);
        // legfwd (batch m): C'[c2][l] = xfh[m] @ legfT[m]  -> cfh[l][c2][m]
        k_hgemm<2, false, false, false, false><<<gLF, 256, SMEMSZ>>>(
            xfh, legfT, nullptr, nullptr, nullptr, nullptr, 512, 96, H_, 184,
            (long)512 * 184, (long)184 * 96, 0);
        cudaStreamWaitEvent(0, evA2[i], 0);
        k_hgemm<3, false, false, false, false><<<gSP, 256, SMEMSZ>>>(
            A2 + (long)i * LM_ * 512 * 512, cfh, nullptr, nullptr, nullptr, nullptr,
            512, 96, 512, 512, (long)512 * 512, (long)512 * 96, 0);
        k_hgemm<4, false, false, false, false><<<gLI, 256, SMEMSZ>>>(
            cf2h, legiH, nullptr, nullptr, nullptr, nullptr, 512, 184, LM_, 96,
            (long)512 * 96, (long)LM_ * 184, 0);
        // irfft + inner skip fused: hBh = fp16( irfft(xf2h) + Ph )
        cudaStreamWaitEvent(0, evP[i], 0);
        k_hgemm<0, false, false, false, true, true><<<gIR, 256, SMEMSZ>>>(
            xf2h, Gih, nullptr, nullptr, hBh, Ph, 46080, W_, 182, 184, 0, 0, 0);
        // t_h = fp16( gelu(w_mlp1 @ hBh) )
        k_hgemm<0, true, false, false, true><<<gH, 256, SMEMSZ>>>(
            wM1 + (long)i * HID_ * E_, hBh, nullptr, nullptr, tH, nullptr,
            HID_, HW, E_, E_, 0, 0, 0);
        // hA(+hAh) = w_mlp2 @ t_h + hA  (last layer: fp16 only)
        if (i + 1 < NLAY)
            k_hgemm<0, false, true, true, true><<<gE, 256, SMEMSZ>>>(
                wM2 + (long)i * E_ * HID_, tH, hA, hA, hAh, nullptr,
                E_, HW, HID_, HID_, 0, 0, 0);
        else
            k_hgemm<0, false, true, false, true><<<gE, 256, SMEMSZ>>>(
                wM2 + (long)i * E_ * HID_, tH, nullptr, hA, hAh, nullptr,
                E_, HW, HID_, HID_, 0, 0, 0);
        if (i + 1 < NLAY) cudaEventRecord(evL[i + 1], 0);
    }

    k_hgemm<0, true, false, false, true><<<gE, 256, SMEMSZ>>>(wDec1, hAh, nullptr, nullptr,
                                                              tH, nullptr, E_, HW, 258, 264, 0, 0, 0);
    k_dec2<<<(HW / 2 + 255) / 256, 256>>>(dec_w2, out);
}

// round 13
// speedup vs baseline: 1.2425x; 1.1401x over previous
#include <cuda_runtime.h>
#include <cuda_fp16.h>
#include <math.h>

#define HW   64800
#define E_   256
#define NLAY 4
#define LM_  90
#define MM_  91
#define HID_ 512
#define H_   180
#define W_   360
#define STG  4
#define SMEMSZ (STG * (128 * 40 + 32 * 136) * 2)

// ---------------- scratch (device globals) ----------------
__device__ float  g_hA[E_ * HW];           // fp32 h (residual)
__device__ __half g_P_h[E_ * HW];          // fp16 inner-skip product (side stream)
__device__ __half g_hA_h[(E_ + 2) * HW];   // fp16 h; rows 256,257 = raw x
__device__ __half g_hB_h[E_ * HW];
__device__ __half g_t_h [HID_ * HW];
__device__ __half g_xfh [MM_ * 512 * 184]; // rfft out: [m][2c+ri][y pad184]
__device__ __half g_cfh [LM_ * 512 * 96];  // legfwd out: [l][2c+ri][m] (m pad 96)
__device__ __half g_cf2h[MM_ * 512 * 96];  // spectral out: [m][o2][l] (l pad 96)
__device__ __half g_xf2h[184 * 46080];     // leginv out: [2m+ri][(o*180+y)]  (k-major!)
__device__ __half g_F_h [W_ * 184];        // rfft DFT [x][2m+ri]
__device__ __half g_Gi_h[182 * W_];        // irfft DFT [2m+ri][x]
__device__ __half g_legfT_h[MM_ * 184 * 96];            // fwd Legendre, [m][y pad184][l pad96]
__device__ __half g_legi_h[MM_ * LM_ * 184];            // inv Legendre, [m][l][h pad184]
__device__ __half g_A2[NLAY][LM_ * 512 * 512];  // spectral fp16 weights, all layers
// fp16 weights
__device__ __half g_w_enc2[E_ * E_];
__device__ __half g_w_inner[NLAY * E_ * E_];
__device__ __half g_w_mlp1[NLAY * HID_ * E_];
__device__ __half g_w_mlp2[NLAY * E_ * HID_];
__device__ __half g_w_dec1[E_ * 264];

__device__ __forceinline__ float gelu_f(float v) {
    return 0.5f * v * (1.0f + erff(v * 0.7071067811865475f));
}
__device__ __forceinline__ unsigned smem_u32(const void* p) {
    return (unsigned)__cvta_generic_to_shared(p);
}
__device__ __forceinline__ void cp16(void* s, const void* g, bool p) {
    unsigned sa = smem_u32(s);
    asm volatile("cp.async.cg.shared.global [%0],[%1],16,%2;\n"
                 :: "r"(sa), "l"(g), "r"(p ? 16 : 0));
}

// ---------------- DFT tables ----------------
__global__ void k_init_tables() {
    int idx = blockIdx.x * blockDim.x + threadIdx.x;
    if (idx < W_ * 184) {
        int x = idx / 184, col = idx % 184;
        float v = 0.f;
        if (col < 182) {
            int m = col >> 1, ri = col & 1;
            int r = (m * x) % W_;
            double s, c;
            sincospi((double)r / 180.0, &s, &c);
            v = ri ? (float)(-s) : (float)c;
        }
        g_F_h[idx] = __float2half(v);
    }
    if (idx < 182 * W_) {
        int k = idx / W_, x = idx % W_;
        int m = k >> 1, ri = k & 1;
        int r = (m * x) % W_;
        double s, c;
        sincospi((double)r / 180.0, &s, &c);
        double sc = (m == 0) ? (1.0 / 360.0) : (2.0 / 360.0);
        g_Gi_h[idx] = __float2half(ri ? (float)(-sc * s) : (float)(sc * c));
    }
}

__global__ void k_zero_cfh() {
    int i = blockIdx.x * blockDim.x + threadIdx.x;
    if (i < LM_ * 512 * 96 / 8) ((uint4*)g_cfh)[i] = make_uint4(0, 0, 0, 0);
}

// fwd Legendre transposed: legfT[m][y][l] = legf[m][l][y], zero-padded (y->184, l->96)
__global__ void k_cast_legfT(const float* __restrict__ s) {
    int i = blockIdx.x * blockDim.x + threadIdx.x;
    if (i >= MM_ * 184 * 96) return;
    int l = i % 96, y = (i / 96) % 184, m = i / (96 * 184);
    float v = (l < LM_ && y < H_) ? s[((long)m * LM_ + l) * H_ + y] : 0.f;
    g_legfT_h[i] = __float2half(v);
}

// inv Legendre: [m][l][h<180] -> fp16 [m][l][184], pad 0
__global__ void k_cast_leg(const float* __restrict__ s, __half* __restrict__ d) {
    int i = blockIdx.x * blockDim.x + threadIdx.x;
    if (i >= MM_ * LM_ * 184) return;
    int col = i % 184, row = i / 184;
    d[i] = (col < H_) ? __float2half(s[row * H_ + col]) : __half(0);
}

// transpose-tiled spectral weight build
__global__ void k_buildA2_t(const float* __restrict__ wr, const float* __restrict__ wi, int slot) {
    int o  = blockIdx.z;
    int c0 = blockIdx.x * 32;
    int l0 = blockIdx.y * 32;
    __shared__ float sr[32][33], si[32][33];
    int tx = threadIdx.x, ty = threadIdx.y;
    #pragma unroll
    for (int i = 0; i < 32; i += 8) {
        int c = c0 + ty + i, l = l0 + tx;
        long base = ((long)o * E_ + c) * LM_ + l;
        bool ok = (l < LM_);
        sr[ty + i][tx] = ok ? wr[base] : 0.f;
        si[ty + i][tx] = ok ? wi[base] : 0.f;
    }
    __syncthreads();
    int c = c0 + tx;
    #pragma unroll
    for (int j = 0; j < 32; j += 8) {
        int l = l0 + ty + j;
        if (l >= LM_) break;
        float r  = sr[tx][ty + j];
        float im = si[tx][ty + j];
        long b0 = ((long)l * 512 + o) * 512 + 2 * c;
        long b1 = ((long)l * 512 + o + 256) * 512 + 2 * c;
        *(__half2*)&g_A2[slot][b0] = __floats2half2_rn(r, -im);
        *(__half2*)&g_A2[slot][b1] = __floats2half2_rn(im, r);
    }
}

// ---------------- casts ----------------
__global__ void k_castw(const float* __restrict__ s, __half* __restrict__ d, int n) {
    int i = blockIdx.x * blockDim.x + threadIdx.x;
    if (i < n) d[i] = __float2half(s[i]);
}
__global__ void k_cast_dec1(const float* __restrict__ s) {
    int i = blockIdx.x * blockDim.x + threadIdx.x;
    if (i >= E_ * 264) return;
    int r = i / 264, c = i % 264;
    g_w_dec1[i] = (c < 258) ? __float2half(s[r * 258 + c]) : __half(0);
}
__global__ void k_castx(const float* __restrict__ x) {
    int i = blockIdx.x * blockDim.x + threadIdx.x;
    if (i < 2 * HW) g_hA_h[E_ * HW + i] = __float2half(x[i]);
}

// encoder stage 1: 2 pixels/thread, half2 stores
__global__ void k_enc1(const float* __restrict__ x, const float* __restrict__ w) {
    int p = (blockIdx.x * blockDim.x + threadIdx.x) * 2;
    if (p >= HW) return;
    float x0a = x[p],      x1a = x[HW + p];
    float x0b = x[p + 1],  x1b = x[HW + p + 1];
    #pragma unroll 4
    for (int e = 0; e < E_; e++) {
        float w0 = w[2 * e], w1 = w[2 * e + 1];
        float va = gelu_f(w0 * x0a + w1 * x1a);
        float vb = gelu_f(w0 * x0b + w1 * x1b);
        *(__half2*)&g_hB_h[e * HW + p] = __floats2half2_rn(va, vb);
    }
}

// ---------------- fp16 tensor-core GEMM, 4-stage cp.async ----------------
// MODE 0: std epilogue. 1: rfft -> g_xfh [m][c2][y]. 2: legfwd -> g_cfh.
// 3: spectral -> g_cf2h. 4: leginv -> g_xf2h [k][(o,y)] coalesced.
// ADDH: add fp16 ADDh tensor. ATRANS: A stored K-major [K][M], lda = M-row stride.
template <int MODE, bool GELU, bool ADDF, bool WF32, bool WF16, bool ADDH = false, bool ATRANS = false>
__global__ __launch_bounds__(256, 2) void k_hgemm(
    const __half* __restrict__ A, const __half* __restrict__ B,
    float* __restrict__ C, const float* __restrict__ ADD, __half* __restrict__ Ch,
    const __half* __restrict__ ADDh,
    int M, int N, int K, int lda, long sA, long sB, long sC) {
    extern __shared__ __half dsm[];
    typedef __half (*AsT)[128][40];
    typedef __half (*AsTt)[32][136];
    typedef __half (*BsT)[32][136];
    AsT  As  = (AsT)dsm;
    AsTt As2 = (AsTt)dsm;                       // overlay (ATRANS layout, smaller)
    BsT  Bs  = (BsT)(dsm + STG * 128 * 40);
    const int tid = threadIdx.x, lane = tid & 31, wid = tid >> 5;
    const int wm = wid >> 2, wn = wid & 3;
    const int bm = blockIdx.y * 128, bn = blockIdx.x * 128;
    const int z = blockIdx.z;
    A += (long)z * sA;
    B += (long)z * sB;
    if (WF32 && MODE == 0) C += (long)z * sC;

    const int r_a = tid >> 1, off_a = (tid & 1) * 16;
    #define LOAD_STAGE(k0, buf)                                                     \
        {                                                                           \
            if (ATRANS) {                                                           \
                _Pragma("unroll")                                                   \
                for (int i = 0; i < 2; i++) {                                       \
                    int idx = tid + i * 256;                                        \
                    int kk = idx >> 4, moff = (idx & 15) * 8;                       \
                    int gk = (k0) + kk;                                             \
                    bool pa = (gk < K);                                             \
                    cp16(&As2[buf][kk][moff],                                       \
                         pa ? A + (long)gk * lda + bm + moff : A, pa);              \
                }                                                                   \
            } else {                                                                \
                const __half* pA = A + (long)(bm + r_a) * lda + (k0) + off_a;       \
                bool pa0 = ((k0) + off_a + 8  <= lda);                              \
                bool pa1 = ((k0) + off_a + 16 <= lda);                              \
                cp16(&As[buf][r_a][off_a],     pa0 ? pA     : A, pa0);              \
                cp16(&As[buf][r_a][off_a + 8], pa1 ? pA + 8 : A, pa1);              \
            }                                                                       \
            _Pragma("unroll")                                                       \
            for (int i = 0; i < 2; i++) {                                           \
                int idx = tid + i * 256;                                            \
                int kk = idx >> 4, noff = (idx & 15) * 8;                           \
                int gk = (k0) + kk, gn = bn + noff;                                 \
                bool pb = (gk < K && gn + 8 <= N);                                  \
                cp16(&Bs[buf][kk][noff], pb ? B + (long)gk * N + gn : B, pb);       \
            }                                                                       \
            asm volatile("cp.async.commit_group;\n" ::);                            \
        }

    float acc[4][4][4];
    #pragma unroll
    for (int i = 0; i < 4; i++)
        #pragma unroll
        for (int j = 0; j < 4; j++)
            #pragma unroll
            for (int q = 0; q < 4; q++) acc[i][j][q] = 0.f;

    LOAD_STAGE(0, 0)
    LOAD_STAGE(32, 1)
    LOAD_STAGE(64, 2)

    const int nslab = (K + 31) / 32;
    for (int it = 0; it < nslab; it++) {
        asm volatile("cp.async.wait_group 2;\n" ::);
        __syncthreads();
        const int buf = it & 3;
        #pragma unroll
        for (int ks = 0; ks < 32; ks += 16) {
            unsigned a[4][4], b[4][2];
            #pragma unroll
            for (int mt = 0; mt < 4; mt++) {
                if (ATRANS) {
                    int m0 = wm * 64 + mt * 16;
                    int krow = ks + ((lane >> 4) & 1) * 8 + (lane & 7);
                    int mcol = m0 + ((lane >> 3) & 1) * 8;
                    unsigned addr = smem_u32(&As2[buf][krow][mcol]);
                    asm volatile("ldmatrix.sync.aligned.m8n8.x4.trans.shared.b16 {%0,%1,%2,%3},[%4];"
                                 : "=r"(a[mt][0]), "=r"(a[mt][1]), "=r"(a[mt][2]), "=r"(a[mt][3])
                                 : "r"(addr));
                } else {
                    unsigned addr = smem_u32(&As[buf][wm * 64 + mt * 16 + (lane & 15)][ks + 8 * (lane >> 4)]);
                    asm volatile("ldmatrix.sync.aligned.m8n8.x4.shared.b16 {%0,%1,%2,%3},[%4];"
                                 : "=r"(a[mt][0]), "=r"(a[mt][1]), "=r"(a[mt][2]), "=r"(a[mt][3])
                                 : "r"(addr));
                }
            }
            #pragma unroll
            for (int nt = 0; nt < 4; nt++) {
                unsigned addr = smem_u32(&Bs[buf][ks + (lane & 15)][wn * 32 + nt * 8]);
                asm volatile("ldmatrix.sync.aligned.m8n8.x2.trans.shared.b16 {%0,%1},[%2];"
                             : "=r"(b[nt][0]), "=r"(b[nt][1])
                             : "r"(addr));
            }
            #pragma unroll
            for (int mt = 0; mt < 4; mt++)
                #pragma unroll
                for (int nt = 0; nt < 4; nt++)
                    asm volatile(
                        "mma.sync.aligned.m16n8k16.row.col.f32.f16.f16.f32 "
                        "{%0,%1,%2,%3},{%4,%5,%6,%7},{%8,%9},{%0,%1,%2,%3};"
                        : "+f"(acc[mt][nt][0]), "+f"(acc[mt][nt][1]),
                          "+f"(acc[mt][nt][2]), "+f"(acc[mt][nt][3])
                        : "r"(a[mt][0]), "r"(a[mt][1]), "r"(a[mt][2]), "r"(a[mt][3]),
                          "r"(b[nt][0]), "r"(b[nt][1]));
        }
        __syncthreads();
        int k0n = (it + 3) * 32;
        if (k0n < K) {
            LOAD_STAGE(k0n, (it + 3) & 3)
        } else {
            asm volatile("cp.async.commit_group;\n" ::);
        }
    }
    #undef LOAD_STAGE

    const int g = lane >> 2, tq = lane & 3;
    #pragma unroll
    for (int mt = 0; mt < 4; mt++) {
        #pragma unroll
        for (int hh = 0; hh < 2; hh++) {
            int gm = bm + wm * 64 + mt * 16 + g + hh * 8;
            float vv0, vv1;
            #pragma unroll
            for (int nt = 0; nt < 4; nt++) {
                int gn = bn + wn * 32 + nt * 8 + tq * 2;
                vv0 = acc[mt][nt][hh * 2 + 0];
                vv1 = acc[mt][nt][hh * 2 + 1];
                if (MODE == 1) {
                    if (gn < 2 * MM_) {
                        int m = gn >> 1;
                        int c = gm / H_, y = gm - c * H_;
                        long base = (long)m * (512 * 184) + (2 * c) * 184 + y;
                        g_xfh[base]       = __float2half(vv0);
                        g_xfh[base + 184] = __float2half(vv1);
                    }
                } else if (MODE == 2) {
                    if (gn < LM_)
                        g_cfh[((long)gn * 512 + gm) * 96 + z] = __float2half(vv0);
                    if (gn + 1 < LM_)
                        g_cfh[((long)(gn + 1) * 512 + gm) * 96 + z] = __float2half(vv1);
                } else if (MODE == 3) {
                    if (gn < MM_)
                        g_cf2h[((long)gn * 512 + gm) * 96 + z] = __float2half(vv0);
                    if (gn + 1 < MM_)
                        g_cf2h[((long)(gn + 1) * 512 + gm) * 96 + z] = __float2half(vv1);
                } else if (MODE == 4) {
                    // k-major coalesced: xf2h[2z+ri][oo*180 + h], h=gn even
                    int oo = gm & 255, ri = gm >> 8;
                    if (gn + 1 < H_) {
                        long addr = (long)(2 * z + ri) * 46080 + oo * H_ + gn;
                        *(__half2*)&g_xf2h[addr] = __floats2half2_rn(vv0, vv1);
                    }
                } else {
                    if (gm >= M || gn >= N) continue;
                    if (GELU) { vv0 = gelu_f(vv0); vv1 = gelu_f(vv1); }
                    if (ADDF) {
                        float2 ad = *(const float2*)&ADD[(long)gm * N + gn];
                        vv0 += ad.x; vv1 += ad.y;
                    }
                    if (ADDH) {
                        __half2 ah = *(const __half2*)&ADDh[(long)gm * N + gn];
                        float2 af = __half22float2(ah);
                        vv0 += af.x; vv1 += af.y;
                    }
                    if (WF32) *(float2*)&C[(long)gm * N + gn] = make_float2(vv0, vv1);
                    if (WF16) *(__half2*)&Ch[(long)gm * N + gn] = __floats2half2_rn(vv0, vv1);
                }
            }
        }
    }
}

// decoder stage 2: 2 pixels/thread, half2 loads
__global__ void k_dec2(const float* __restrict__ w, float* __restrict__ out) {
    int p = (blockIdx.x * blockDim.x + threadIdx.x) * 2;
    if (p >= HW) return;
    float a0 = 0.f, a1 = 0.f, b0 = 0.f, b1 = 0.f;
    #pragma unroll 4
    for (int c = 0; c < E_; c++) {
        __half2 vh = *(const __half2*)&g_t_h[c * HW + p];
        float2 vf = __half22float2(vh);
        float w0 = w[c], w1 = w[E_ + c];
        a0 += w0 * vf.x; b0 += w0 * vf.y;
        a1 += w1 * vf.x; b1 += w1 * vf.y;
    }
    out[p] = a0;       out[p + 1] = b0;
    out[HW + p] = a1;  out[HW + p + 1] = b1;
}

extern "C" void kernel_launch(void* const* d_in, const int* in_sizes, int n_in,
                              void* d_out, int out_size) {
    const float* x        = (const float*)d_in[0];
    const float* enc_w1   = (const float*)d_in[1];
    const float* enc_w2   = (const float*)d_in[2];
    const float* pos      = (const float*)d_in[3];
    const float* leg_fwd  = (const float*)d_in[4];
    const float* leg_inv  = (const float*)d_in[5];
    const float* w_spec_r = (const float*)d_in[6];
    const float* w_spec_i = (const float*)d_in[7];
    const float* w_inner  = (const float*)d_in[8];
    const float* w_mlp1   = (const float*)d_in[9];
    const float* w_mlp2   = (const float*)d_in[10];
    const float* dec_w1   = (const float*)d_in[11];
    const float* dec_w2   = (const float*)d_in[12];
    float* out = (float*)d_out;

    float* hA;
    __half *Ph, *hAh, *hBh, *tH, *wEnc2, *wInn, *wM1, *wM2, *wDec1;
    __half *Fh, *Gih, *xfh, *cfh, *cf2h, *xf2h, *legfT, *legiH, *A2;
    cudaGetSymbolAddress((void**)&hA, g_hA);
    cudaGetSymbolAddress((void**)&Ph, g_P_h);
    cudaGetSymbolAddress((void**)&hAh, g_hA_h);
    cudaGetSymbolAddress((void**)&hBh, g_hB_h);
    cudaGetSymbolAddress((void**)&tH, g_t_h);
    cudaGetSymbolAddress((void**)&wEnc2, g_w_enc2);
    cudaGetSymbolAddress((void**)&wInn, g_w_inner);
    cudaGetSymbolAddress((void**)&wM1, g_w_mlp1);
    cudaGetSymbolAddress((void**)&wM2, g_w_mlp2);
    cudaGetSymbolAddress((void**)&wDec1, g_w_dec1);
    cudaGetSymbolAddress((void**)&Fh, g_F_h);
    cudaGetSymbolAddress((void**)&Gih, g_Gi_h);
    cudaGetSymbolAddress((void**)&xfh, g_xfh);
    cudaGetSymbolAddress((void**)&cfh, g_cfh);
    cudaGetSymbolAddress((void**)&cf2h, g_cf2h);
    cudaGetSymbolAddress((void**)&xf2h, g_xf2h);
    cudaGetSymbolAddress((void**)&legfT, g_legfT_h);
    cudaGetSymbolAddress((void**)&legiH, g_legi_h);
    cudaGetSymbolAddress((void**)&A2, g_A2);

    cudaFuncSetAttribute(k_hgemm<0, false, true,  true,  true >, cudaFuncAttributeMaxDynamicSharedMemorySize, SMEMSZ);
    cudaFuncSetAttribute(k_hgemm<0, false, true,  false, true >, cudaFuncAttributeMaxDynamicSharedMemorySize, SMEMSZ);
    cudaFuncSetAttribute(k_hgemm<0, true,  false, false, true >, cudaFuncAttributeMaxDynamicSharedMemorySize, SMEMSZ);
    cudaFuncSetAttribute(k_hgemm<0, false, false, false, true >, cudaFuncAttributeMaxDynamicSharedMemorySize, SMEMSZ);
    cudaFuncSetAttribute(k_hgemm<0, false, false, false, true, true, true>, cudaFuncAttributeMaxDynamicSharedMemorySize, SMEMSZ);
    cudaFuncSetAttribute(k_hgemm<1, false, false, false, false>, cudaFuncAttributeMaxDynamicSharedMemorySize, SMEMSZ);
    cudaFuncSetAttribute(k_hgemm<2, false, false, false, false>, cudaFuncAttributeMaxDynamicSharedMemorySize, SMEMSZ);
    cudaFuncSetAttribute(k_hgemm<3, false, false, false, false>, cudaFuncAttributeMaxDynamicSharedMemorySize, SMEMSZ);
    cudaFuncSetAttribute(k_hgemm<4, false, false, false, false>, cudaFuncAttributeMaxDynamicSharedMemorySize, SMEMSZ);

    static cudaStream_t s1 = nullptr, s2 = nullptr;
    static cudaEvent_t evRoot, evInit, evW, evA2[NLAY], evL[NLAY], evP[NLAY];
    if (!s1) {
        cudaStreamCreateWithFlags(&s1, cudaStreamNonBlocking);
        cudaStreamCreateWithFlags(&s2, cudaStreamNonBlocking);
        cudaEventCreateWithFlags(&evRoot, cudaEventDisableTiming);
        cudaEventCreateWithFlags(&evInit, cudaEventDisableTiming);
        cudaEventCreateWithFlags(&evW, cudaEventDisableTiming);
        for (int i = 0; i < NLAY; i++) {
            cudaEventCreateWithFlags(&evA2[i], cudaEventDisableTiming);
            cudaEventCreateWithFlags(&evL[i], cudaEventDisableTiming);
            cudaEventCreateWithFlags(&evP[i], cudaEventDisableTiming);
        }
    }

    const int NB = (HW + 127) / 128;   // 507
    dim3 gE(NB, E_ / 128);
    dim3 gH(NB, HID_ / 128);
    dim3 gRF(2, 360);                  // rfft:   M=46080, N=184
    dim3 gLF(1, 4, MM_);               // legfwd: M=512, N=96, batch m
    dim3 gSP(1, 4, LM_);               // spectral: M=512, N=96, batch l
    dim3 gLI(2, 4, MM_);               // leginv: M=512, N=184, batch m
    dim3 gIR(3, 360);                  // irfft:  M=46080, N=360, ATRANS A
    dim3 gB2(8, 3, 256), bB2(32, 8);

    // ---- fork init stream ----
    cudaEventRecord(evRoot, 0);
    cudaStreamWaitEvent(s1, evRoot, 0);
    k_castw<<<(E_ * E_ + 255) / 256, 256, 0, s1>>>(enc_w2, wEnc2, E_ * E_);
    cudaEventRecord(evW, s1);
    k_castw<<<(NLAY * E_ * E_ + 255) / 256, 256, 0, s1>>>(w_inner, wInn, NLAY * E_ * E_);
    k_castw<<<(NLAY * HID_ * E_ + 255) / 256, 256, 0, s1>>>(w_mlp1, wM1, NLAY * HID_ * E_);
    k_castw<<<(NLAY * E_ * HID_ + 255) / 256, 256, 0, s1>>>(w_mlp2, wM2, NLAY * E_ * HID_);
    k_init_tables<<<(W_ * 184 + 255) / 256, 256, 0, s1>>>();
    k_zero_cfh<<<(LM_ * 512 * 96 / 8 + 255) / 256, 256, 0, s1>>>();
    k_cast_legfT<<<(MM_ * 184 * 96 + 255) / 256, 256, 0, s1>>>(leg_fwd);
    k_cast_leg<<<(MM_ * LM_ * 184 + 255) / 256, 256, 0, s1>>>(leg_inv, legiH);
    k_cast_dec1<<<(E_ * 264 + 255) / 256, 256, 0, s1>>>(dec_w1);
    k_castx<<<(2 * HW + 255) / 256, 256, 0, s1>>>(x);
    cudaEventRecord(evInit, s1);
    for (int i = 0; i < NLAY; i++) {
        k_buildA2_t<<<gB2, bB2, 0, s1>>>(w_spec_r + (long)i * E_ * E_ * LM_,
                                         w_spec_i + (long)i * E_ * E_ * LM_, i);
        cudaEventRecord(evA2[i], s1);
    }

    // ---- main: encoder ----
    k_enc1<<<(HW / 2 + 255) / 256, 256>>>(x, enc_w1);
    cudaStreamWaitEvent(0, evW, 0);
    k_hgemm<0, false, true, true, true><<<gE, 256, SMEMSZ>>>(wEnc2, hBh, hA, pos, hAh,
                                                             nullptr, E_, HW, E_, E_, 0, 0, 0);
    cudaEventRecord(evL[0], 0);
    cudaStreamWaitEvent(0, evInit, 0);

    for (int i = 0; i < NLAY; i++) {
        // side s2: Ph = fp16( w_inner[i] @ hAh ), concurrent with spectral chain
        cudaStreamWaitEvent(s2, evL[i], 0);
        if (i == 0) cudaStreamWaitEvent(s2, evInit, 0);
        k_hgemm<0, false, false, false, true><<<gE, 256, SMEMSZ, s2>>>(
            wInn + (long)i * E_ * E_, hAh, nullptr, nullptr, Ph, nullptr,
            E_, HW, E_, E_, 0, 0, 0);
        cudaEventRecord(evP[i], s2);

        // main: spectral chain
        k_hgemm<1, false, false, false, false><<<gRF, 256, SMEMSZ>>>(
            hAh, Fh, nullptr, nullptr, nullptr, nullptr, 46080, 184, W_, W_, 0, 0, 0);
        k_hgemm<2, false, false, false, false><<<gLF, 256, SMEMSZ>>>(
            xfh, legfT, nullptr, nullptr, nullptr, nullptr, 512, 96, H_, 184,
            (long)512 * 184, (long)184 * 96, 0);
        cudaStreamWaitEvent(0, evA2[i], 0);
        k_hgemm<3, false, false, false, false><<<gSP, 256, SMEMSZ>>>(
            A2 + (long)i * LM_ * 512 * 512, cfh, nullptr, nullptr, nullptr, nullptr,
            512, 96, 512, 512, (long)512 * 512, (long)512 * 96, 0);
        // leginv -> xf2h[k][(o,y)] coalesced
        k_hgemm<4, false, false, false, false><<<gLI, 256, SMEMSZ>>>(
            cf2h, legiH, nullptr, nullptr, nullptr, nullptr, 512, 184, LM_, 96,
            (long)512 * 96, (long)LM_ * 184, 0);
        // irfft (ATRANS A) + inner skip fused: hBh = fp16( irfft(xf2h) + Ph )
        cudaStreamWaitEvent(0, evP[i], 0);
        k_hgemm<0, false, false, false, true, true, true><<<gIR, 256, SMEMSZ>>>(
            xf2h, Gih, nullptr, nullptr, hBh, Ph, 46080, W_, 182, 46080, 0, 0, 0);
        // t_h = fp16( gelu(w_mlp1 @ hBh) )
        k_hgemm<0, true, false, false, true><<<gH, 256, SMEMSZ>>>(
            wM1 + (long)i * HID_ * E_, hBh, nullptr, nullptr, tH, nullptr,
            HID_, HW, E_, E_, 0, 0, 0);
        // hA(+hAh) = w_mlp2 @ t_h + hA  (last layer: fp16 only)
        if (i + 1 < NLAY)
            k_hgemm<0, false, true, true, true><<<gE, 256, SMEMSZ>>>(
                wM2 + (long)i * E_ * HID_, tH, hA, hA, hAh, nullptr,
                E_, HW, HID_, HID_, 0, 0, 0);
        else
            k_hgemm<0, false, true, false, true><<<gE, 256, SMEMSZ>>>(
                wM2 + (long)i * E_ * HID_, tH, nullptr, hA, hAh, nullptr,
                E_, HW, HID_, HID_, 0, 0, 0);
        if (i + 1 < NLAY) cudaEventRecord(evL[i + 1], 0);
    }

    k_hgemm<0, true, false, false, true><<<gE, 256, SMEMSZ>>>(wDec1, hAh, nullptr, nullptr,
                                                              tH, nullptr, E_, HW, 258, 264, 0, 0, 0);
    k_dec2<<<(HW / 2 + 255) / 256, 256>>>(dec_w2, out);
}

// round 14
// speedup vs baseline: 1.2945x; 1.0418x over previous
#include <cuda_runtime.h>
#include <cuda_fp16.h>
#include <math.h>

#define HW   64800
#define E_   256
#define NLAY 4
#define LM_  90
#define MM_  91
#define HID_ 512
#define H_   180
#define W_   360
#define STG  3
#define ASZ  (128 * 72)
#define BSZ  (64 * 136)
#define SMEMSZ (STG * (ASZ + BSZ) * 2)

// ---------------- scratch (device globals) ----------------
__device__ float  g_hA[E_ * HW];           // fp32 h (residual)
__device__ __half g_P_h[E_ * HW];          // fp16 inner-skip product (side stream)
__device__ __half g_hA_h[(E_ + 2) * HW];   // fp16 h; rows 256,257 = raw x
__device__ __half g_hB_h[E_ * HW];
__device__ __half g_t_h [HID_ * HW];
__device__ __half g_xfh [MM_ * 512 * 184]; // rfft out: [m][2c+ri][y pad184]
__device__ __half g_cfh [LM_ * 512 * 96];  // legfwd out: [l][2c+ri][m] (m pad 96)
__device__ __half g_cf2h[MM_ * 512 * 96];  // spectral out: [m][o2][l] (l pad 96)
__device__ __half g_xf2h[184 * 46080];     // leginv out: [2m+ri][(o*180+y)]  (k-major)
__device__ __half g_F_h [W_ * 184];        // rfft DFT [x][2m+ri]
__device__ __half g_Gi_h[182 * W_];        // irfft DFT [2m+ri][x]
__device__ __half g_legfT_h[MM_ * 184 * 96];            // fwd Legendre, [m][y pad184][l pad96]
__device__ __half g_legi_h[MM_ * LM_ * 184];            // inv Legendre, [m][l][h pad184]
__device__ __half g_A2[NLAY][LM_ * 512 * 512];  // spectral fp16 weights, all layers
// fp16 weights
__device__ __half g_w_enc2[E_ * E_];
__device__ __half g_w_inner[NLAY * E_ * E_];
__device__ __half g_w_mlp1[NLAY * HID_ * E_];
__device__ __half g_w_mlp2[NLAY * E_ * HID_];
__device__ __half g_w_dec1[E_ * 264];

__device__ __forceinline__ float gelu_f(float v) {
    return 0.5f * v * (1.0f + erff(v * 0.7071067811865475f));
}
__device__ __forceinline__ unsigned smem_u32(const void* p) {
    return (unsigned)__cvta_generic_to_shared(p);
}
__device__ __forceinline__ void cp16(void* s, const void* g, bool p) {
    unsigned sa = smem_u32(s);
    asm volatile("cp.async.cg.shared.global [%0],[%1],16,%2;\n"
                 :: "r"(sa), "l"(g), "r"(p ? 16 : 0));
}

// ---------------- DFT tables ----------------
__global__ void k_init_tables() {
    int idx = blockIdx.x * blockDim.x + threadIdx.x;
    if (idx < W_ * 184) {
        int x = idx / 184, col = idx % 184;
        float v = 0.f;
        if (col < 182) {
            int m = col >> 1, ri = col & 1;
            int r = (m * x) % W_;
            double s, c;
            sincospi((double)r / 180.0, &s, &c);
            v = ri ? (float)(-s) : (float)c;
        }
        g_F_h[idx] = __float2half(v);
    }
    if (idx < 182 * W_) {
        int k = idx / W_, x = idx % W_;
        int m = k >> 1, ri = k & 1;
        int r = (m * x) % W_;
        double s, c;
        sincospi((double)r / 180.0, &s, &c);
        double sc = (m == 0) ? (1.0 / 360.0) : (2.0 / 360.0);
        g_Gi_h[idx] = __float2half(ri ? (float)(-sc * s) : (float)(sc * c));
    }
}

__global__ void k_zero_cfh() {
    int i = blockIdx.x * blockDim.x + threadIdx.x;
    if (i < LM_ * 512 * 96 / 8) ((uint4*)g_cfh)[i] = make_uint4(0, 0, 0, 0);
}

// fwd Legendre transposed: legfT[m][y][l] = legf[m][l][y], zero-padded (y->184, l->96)
__global__ void k_cast_legfT(const float* __restrict__ s) {
    int i = blockIdx.x * blockDim.x + threadIdx.x;
    if (i >= MM_ * 184 * 96) return;
    int l = i % 96, y = (i / 96) % 184, m = i / (96 * 184);
    float v = (l < LM_ && y < H_) ? s[((long)m * LM_ + l) * H_ + y] : 0.f;
    g_legfT_h[i] = __float2half(v);
}

// inv Legendre: [m][l][h<180] -> fp16 [m][l][184], pad 0
__global__ void k_cast_leg(const float* __restrict__ s, __half* __restrict__ d) {
    int i = blockIdx.x * blockDim.x + threadIdx.x;
    if (i >= MM_ * LM_ * 184) return;
    int col = i % 184, row = i / 184;
    d[i] = (col < H_) ? __float2half(s[row * H_ + col]) : __half(0);
}

// transpose-tiled spectral weight build
__global__ void k_buildA2_t(const float* __restrict__ wr, const float* __restrict__ wi, int slot) {
    int o  = blockIdx.z;
    int c0 = blockIdx.x * 32;
    int l0 = blockIdx.y * 32;
    __shared__ float sr[32][33], si[32][33];
    int tx = threadIdx.x, ty = threadIdx.y;
    #pragma unroll
    for (int i = 0; i < 32; i += 8) {
        int c = c0 + ty + i, l = l0 + tx;
        long base = ((long)o * E_ + c) * LM_ + l;
        bool ok = (l < LM_);
        sr[ty + i][tx] = ok ? wr[base] : 0.f;
        si[ty + i][tx] = ok ? wi[base] : 0.f;
    }
    __syncthreads();
    int c = c0 + tx;
    #pragma unroll
    for (int j = 0; j < 32; j += 8) {
        int l = l0 + ty + j;
        if (l >= LM_) break;
        float r  = sr[tx][ty + j];
        float im = si[tx][ty + j];
        long b0 = ((long)l * 512 + o) * 512 + 2 * c;
        long b1 = ((long)l * 512 + o + 256) * 512 + 2 * c;
        *(__half2*)&g_A2[slot][b0] = __floats2half2_rn(r, -im);
        *(__half2*)&g_A2[slot][b1] = __floats2half2_rn(im, r);
    }
}

// ---------------- casts ----------------
__global__ void k_castw(const float* __restrict__ s, __half* __restrict__ d, int n) {
    int i = blockIdx.x * blockDim.x + threadIdx.x;
    if (i < n) d[i] = __float2half(s[i]);
}
__global__ void k_cast_dec1(const float* __restrict__ s) {
    int i = blockIdx.x * blockDim.x + threadIdx.x;
    if (i >= E_ * 264) return;
    int r = i / 264, c = i % 264;
    g_w_dec1[i] = (c < 258) ? __float2half(s[r * 258 + c]) : __half(0);
}
__global__ void k_castx(const float* __restrict__ x) {
    int i = blockIdx.x * blockDim.x + threadIdx.x;
    if (i < 2 * HW) g_hA_h[E_ * HW + i] = __float2half(x[i]);
}

// encoder stage 1: 2 pixels/thread, half2 stores
__global__ void k_enc1(const float* __restrict__ x, const float* __restrict__ w) {
    int p = (blockIdx.x * blockDim.x + threadIdx.x) * 2;
    if (p >= HW) return;
    float x0a = x[p],      x1a = x[HW + p];
    float x0b = x[p + 1],  x1b = x[HW + p + 1];
    #pragma unroll 4
    for (int e = 0; e < E_; e++) {
        float w0 = w[2 * e], w1 = w[2 * e + 1];
        float va = gelu_f(w0 * x0a + w1 * x1a);
        float vb = gelu_f(w0 * x0b + w1 * x1b);
        *(__half2*)&g_hB_h[e * HW + p] = __floats2half2_rn(va, vb);
    }
}

// ---------------- fp16 tensor-core GEMM, BK=64, 3-stage cp.async ----------------
// MODE 0: std epilogue. 1: rfft -> g_xfh [m][c2][y]. 2: legfwd -> g_cfh.
// 3: spectral -> g_cf2h. 4: leginv -> g_xf2h [k][(o,y)] coalesced.
// ADDH: add fp16 ADDh tensor. ATRANS: A stored K-major [K][M], lda = M-row stride.
template <int MODE, bool GELU, bool ADDF, bool WF32, bool WF16, bool ADDH = false, bool ATRANS = false>
__global__ __launch_bounds__(256, 2) void k_hgemm(
    const __half* __restrict__ A, const __half* __restrict__ B,
    float* __restrict__ C, const float* __restrict__ ADD, __half* __restrict__ Ch,
    const __half* __restrict__ ADDh,
    int M, int N, int K, int lda, long sA, long sB, long sC) {
    extern __shared__ __half dsm[];
    typedef __half (*AsT)[128][72];
    typedef __half (*AsTt)[64][136];
    typedef __half (*BsT)[64][136];
    AsT  As  = (AsT)dsm;
    AsTt As2 = (AsTt)dsm;                       // overlay (ATRANS layout, smaller)
    BsT  Bs  = (BsT)(dsm + STG * ASZ);
    const int tid = threadIdx.x, lane = tid & 31, wid = tid >> 5;
    const int wm = wid >> 2, wn = wid & 3;
    const int bm = blockIdx.y * 128, bn = blockIdx.x * 128;
    const int z = blockIdx.z;
    A += (long)z * sA;
    B += (long)z * sB;
    if (WF32 && MODE == 0) C += (long)z * sC;

    #define LOAD_STAGE(k0, buf)                                                     \
        {                                                                           \
            if (ATRANS) {                                                           \
                _Pragma("unroll")                                                   \
                for (int i = 0; i < 4; i++) {                                       \
                    int idx = tid + i * 256;                                        \
                    int kk = idx >> 4, moff = (idx & 15) * 8;                       \
                    int gk = (k0) + kk;                                             \
                    bool pa = (gk < K);                                             \
                    cp16(&As2[buf][kk][moff],                                       \
                         pa ? A + (long)gk * lda + bm + moff : A, pa);              \
                }                                                                   \
            } else {                                                                \
                _Pragma("unroll")                                                   \
                for (int i = 0; i < 4; i++) {                                       \
                    int idx = tid + i * 256;                                        \
                    int r = idx >> 3, col = (idx & 7) * 8;                          \
                    bool pa = ((k0) + col + 8 <= lda);                              \
                    cp16(&As[buf][r][col],                                          \
                         pa ? A + (long)(bm + r) * lda + (k0) + col : A, pa);       \
                }                                                                   \
            }                                                                       \
            _Pragma("unroll")                                                       \
            for (int i = 0; i < 4; i++) {                                           \
                int idx = tid + i * 256;                                            \
                int kk = idx >> 4, noff = (idx & 15) * 8;                           \
                int gk = (k0) + kk, gn = bn + noff;                                 \
                bool pb = (gk < K && gn + 8 <= N);                                  \
                cp16(&Bs[buf][kk][noff], pb ? B + (long)gk * N + gn : B, pb);       \
            }                                                                       \
            asm volatile("cp.async.commit_group;\n" ::);                            \
        }

    float acc[4][4][4];
    #pragma unroll
    for (int i = 0; i < 4; i++)
        #pragma unroll
        for (int j = 0; j < 4; j++)
            #pragma unroll
            for (int q = 0; q < 4; q++) acc[i][j][q] = 0.f;

    LOAD_STAGE(0, 0)
    LOAD_STAGE(64, 1)
    LOAD_STAGE(128, 2)

    const int nslab = (K + 63) / 64;
    for (int it = 0; it < nslab; it++) {
        asm volatile("cp.async.wait_group 2;\n" ::);
        __syncthreads();
        const int buf = it % 3;
        #pragma unroll
        for (int ks = 0; ks < 64; ks += 16) {
            unsigned a[4][4], b[4][2];
            #pragma unroll
            for (int mt = 0; mt < 4; mt++) {
                if (ATRANS) {
                    int m0 = wm * 64 + mt * 16;
                    int krow = ks + ((lane >> 4) & 1) * 8 + (lane & 7);
                    int mcol = m0 + ((lane >> 3) & 1) * 8;
                    unsigned addr = smem_u32(&As2[buf][krow][mcol]);
                    asm volatile("ldmatrix.sync.aligned.m8n8.x4.trans.shared.b16 {%0,%1,%2,%3},[%4];"
                                 : "=r"(a[mt][0]), "=r"(a[mt][1]), "=r"(a[mt][2]), "=r"(a[mt][3])
                                 : "r"(addr));
                } else {
                    unsigned addr = smem_u32(&As[buf][wm * 64 + mt * 16 + (lane & 15)][ks + 8 * (lane >> 4)]);
                    asm volatile("ldmatrix.sync.aligned.m8n8.x4.shared.b16 {%0,%1,%2,%3},[%4];"
                                 : "=r"(a[mt][0]), "=r"(a[mt][1]), "=r"(a[mt][2]), "=r"(a[mt][3])
                                 : "r"(addr));
                }
            }
            #pragma unroll
            for (int nt = 0; nt < 4; nt++) {
                unsigned addr = smem_u32(&Bs[buf][ks + (lane & 15)][wn * 32 + nt * 8]);
                asm volatile("ldmatrix.sync.aligned.m8n8.x2.trans.shared.b16 {%0,%1},[%2];"
                             : "=r"(b[nt][0]), "=r"(b[nt][1])
                             : "r"(addr));
            }
            #pragma unroll
            for (int mt = 0; mt < 4; mt++)
                #pragma unroll
                for (int nt = 0; nt < 4; nt++)
                    asm volatile(
                        "mma.sync.aligned.m16n8k16.row.col.f32.f16.f16.f32 "
                        "{%0,%1,%2,%3},{%4,%5,%6,%7},{%8,%9},{%0,%1,%2,%3};"
                        : "+f"(acc[mt][nt][0]), "+f"(acc[mt][nt][1]),
                          "+f"(acc[mt][nt][2]), "+f"(acc[mt][nt][3])
                        : "r"(a[mt][0]), "r"(a[mt][1]), "r"(a[mt][2]), "r"(a[mt][3]),
                          "r"(b[nt][0]), "r"(b[nt][1]));
        }
        __syncthreads();
        int k0n = (it + 3) * 64;
        if (k0n < K) {
            LOAD_STAGE(k0n, (it + 3) % 3)
        } else {
            asm volatile("cp.async.commit_group;\n" ::);
        }
    }
    #undef LOAD_STAGE

    const int g = lane >> 2, tq = lane & 3;
    #pragma unroll
    for (int mt = 0; mt < 4; mt++) {
        #pragma unroll
        for (int hh = 0; hh < 2; hh++) {
            int gm = bm + wm * 64 + mt * 16 + g + hh * 8;
            float vv0, vv1;
            #pragma unroll
            for (int nt = 0; nt < 4; nt++) {
                int gn = bn + wn * 32 + nt * 8 + tq * 2;
                vv0 = acc[mt][nt][hh * 2 + 0];
                vv1 = acc[mt][nt][hh * 2 + 1];
                if (MODE == 1) {
                    if (gn < 2 * MM_) {
                        int m = gn >> 1;
                        int c = gm / H_, y = gm - c * H_;
                        long base = (long)m * (512 * 184) + (2 * c) * 184 + y;
                        g_xfh[base]       = __float2half(vv0);
                        g_xfh[base + 184] = __float2half(vv1);
                    }
                } else if (MODE == 2) {
                    if (gn < LM_)
                        g_cfh[((long)gn * 512 + gm) * 96 + z] = __float2half(vv0);
                    if (gn + 1 < LM_)
                        g_cfh[((long)(gn + 1) * 512 + gm) * 96 + z] = __float2half(vv1);
                } else if (MODE == 3) {
                    if (gn < MM_)
                        g_cf2h[((long)gn * 512 + gm) * 96 + z] = __float2half(vv0);
                    if (gn + 1 < MM_)
                        g_cf2h[((long)(gn + 1) * 512 + gm) * 96 + z] = __float2half(vv1);
                } else if (MODE == 4) {
                    int oo = gm & 255, ri = gm >> 8;
                    if (gn + 1 < H_) {
                        long addr = (long)(2 * z + ri) * 46080 + oo * H_ + gn;
                        *(__half2*)&g_xf2h[addr] = __floats2half2_rn(vv0, vv1);
                    }
                } else {
                    if (gm >= M || gn >= N) continue;
                    if (GELU) { vv0 = gelu_f(vv0); vv1 = gelu_f(vv1); }
                    if (ADDF) {
                        float2 ad = *(const float2*)&ADD[(long)gm * N + gn];
                        vv0 += ad.x; vv1 += ad.y;
                    }
                    if (ADDH) {
                        __half2 ah = *(const __half2*)&ADDh[(long)gm * N + gn];
                        float2 af = __half22float2(ah);
                        vv0 += af.x; vv1 += af.y;
                    }
                    if (WF32) *(float2*)&C[(long)gm * N + gn] = make_float2(vv0, vv1);
                    if (WF16) *(__half2*)&Ch[(long)gm * N + gn] = __floats2half2_rn(vv0, vv1);
                }
            }
        }
    }
}

// decoder stage 2: 2 pixels/thread, half2 loads
__global__ void k_dec2(const float* __restrict__ w, float* __restrict__ out) {
    int p = (blockIdx.x * blockDim.x + threadIdx.x) * 2;
    if (p >= HW) return;
    float a0 = 0.f, a1 = 0.f, b0 = 0.f, b1 = 0.f;
    #pragma unroll 4
    for (int c = 0; c < E_; c++) {
        __half2 vh = *(const __half2*)&g_t_h[c * HW + p];
        float2 vf = __half22float2(vh);
        float w0 = w[c], w1 = w[E_ + c];
        a0 += w0 * vf.x; b0 += w0 * vf.y;
        a1 += w1 * vf.x; b1 += w1 * vf.y;
    }
    out[p] = a0;       out[p + 1] = b0;
    out[HW + p] = a1;  out[HW + p + 1] = b1;
}

extern "C" void kernel_launch(void* const* d_in, const int* in_sizes, int n_in,
                              void* d_out, int out_size) {
    const float* x        = (const float*)d_in[0];
    const float* enc_w1   = (const float*)d_in[1];
    const float* enc_w2   = (const float*)d_in[2];
    const float* pos      = (const float*)d_in[3];
    const float* leg_fwd  = (const float*)d_in[4];
    const float* leg_inv  = (const float*)d_in[5];
    const float* w_spec_r = (const float*)d_in[6];
    const float* w_spec_i = (const float*)d_in[7];
    const float* w_inner  = (const float*)d_in[8];
    const float* w_mlp1   = (const float*)d_in[9];
    const float* w_mlp2   = (const float*)d_in[10];
    const float* dec_w1   = (const float*)d_in[11];
    const float* dec_w2   = (const float*)d_in[12];
    float* out = (float*)d_out;

    float* hA;
    __half *Ph, *hAh, *hBh, *tH, *wEnc2, *wInn, *wM1, *wM2, *wDec1;
    __half *Fh, *Gih, *xfh, *cfh, *cf2h, *xf2h, *legfT, *legiH, *A2;
    cudaGetSymbolAddress((void**)&hA, g_hA);
    cudaGetSymbolAddress((void**)&Ph, g_P_h);
    cudaGetSymbolAddress((void**)&hAh, g_hA_h);
    cudaGetSymbolAddress((void**)&hBh, g_hB_h);
    cudaGetSymbolAddress((void**)&tH, g_t_h);
    cudaGetSymbolAddress((void**)&wEnc2, g_w_enc2);
    cudaGetSymbolAddress((void**)&wInn, g_w_inner);
    cudaGetSymbolAddress((void**)&wM1, g_w_mlp1);
    cudaGetSymbolAddress((void**)&wM2, g_w_mlp2);
    cudaGetSymbolAddress((void**)&wDec1, g_w_dec1);
    cudaGetSymbolAddress((void**)&Fh, g_F_h);
    cudaGetSymbolAddress((void**)&Gih, g_Gi_h);
    cudaGetSymbolAddress((void**)&xfh, g_xfh);
    cudaGetSymbolAddress((void**)&cfh, g_cfh);
    cudaGetSymbolAddress((void**)&cf2h, g_cf2h);
    cudaGetSymbolAddress((void**)&xf2h, g_xf2h);
    cudaGetSymbolAddress((void**)&legfT, g_legfT_h);
    cudaGetSymbolAddress((void**)&legiH, g_legi_h);
    cudaGetSymbolAddress((void**)&A2, g_A2);

    cudaFuncSetAttribute(k_hgemm<0, false, true,  true,  true >, cudaFuncAttributeMaxDynamicSharedMemorySize, SMEMSZ);
    cudaFuncSetAttribute(k_hgemm<0, false, true,  false, true >, cudaFuncAttributeMaxDynamicSharedMemorySize, SMEMSZ);
    cudaFuncSetAttribute(k_hgemm<0, true,  false, false, true >, cudaFuncAttributeMaxDynamicSharedMemorySize, SMEMSZ);
    cudaFuncSetAttribute(k_hgemm<0, false, false, false, true >, cudaFuncAttributeMaxDynamicSharedMemorySize, SMEMSZ);
    cudaFuncSetAttribute(k_hgemm<0, false, false, false, true, true, true>, cudaFuncAttributeMaxDynamicSharedMemorySize, SMEMSZ);
    cudaFuncSetAttribute(k_hgemm<1, false, false, false, false>, cudaFuncAttributeMaxDynamicSharedMemorySize, SMEMSZ);
    cudaFuncSetAttribute(k_hgemm<2, false, false, false, false>, cudaFuncAttributeMaxDynamicSharedMemorySize, SMEMSZ);
    cudaFuncSetAttribute(k_hgemm<3, false, false, false, false>, cudaFuncAttributeMaxDynamicSharedMemorySize, SMEMSZ);
    cudaFuncSetAttribute(k_hgemm<4, false, false, false, false>, cudaFuncAttributeMaxDynamicSharedMemorySize, SMEMSZ);

    static cudaStream_t s1 = nullptr, s2 = nullptr;
    static cudaEvent_t evRoot, evInit, evW, evA2[NLAY], evL[NLAY], evP[NLAY];
    if (!s1) {
        cudaStreamCreateWithFlags(&s1, cudaStreamNonBlocking);
        cudaStreamCreateWithFlags(&s2, cudaStreamNonBlocking);
        cudaEventCreateWithFlags(&evRoot, cudaEventDisableTiming);
        cudaEventCreateWithFlags(&evInit, cudaEventDisableTiming);
        cudaEventCreateWithFlags(&evW, cudaEventDisableTiming);
        for (int i = 0; i < NLAY; i++) {
            cudaEventCreateWithFlags(&evA2[i], cudaEventDisableTiming);
            cudaEventCreateWithFlags(&evL[i], cudaEventDisableTiming);
            cudaEventCreateWithFlags(&evP[i], cudaEventDisableTiming);
        }
    }

    const int NB = (HW + 127) / 128;   // 507
    dim3 gE(NB, E_ / 128);
    dim3 gH(NB, HID_ / 128);
    dim3 gRF(2, 360);                  // rfft:   M=46080, N=184
    dim3 gLF(1, 4, MM_);               // legfwd: M=512, N=96, batch m
    dim3 gSP(1, 4, LM_);               // spectral: M=512, N=96, batch l
    dim3 gLI(2, 4, MM_);               // leginv: M=512, N=184, batch m
    dim3 gIR(3, 360);                  // irfft:  M=46080, N=360, ATRANS A
    dim3 gB2(8, 3, 256), bB2(32, 8);

    // ---- fork init stream ----
    cudaEventRecord(evRoot, 0);
    cudaStreamWaitEvent(s1, evRoot, 0);
    k_castw<<<(E_ * E_ + 255) / 256, 256, 0, s1>>>(enc_w2, wEnc2, E_ * E_);
    cudaEventRecord(evW, s1);
    k_castw<<<(NLAY * E_ * E_ + 255) / 256, 256, 0, s1>>>(w_inner, wInn, NLAY * E_ * E_);
    k_castw<<<(NLAY * HID_ * E_ + 255) / 256, 256, 0, s1>>>(w_mlp1, wM1, NLAY * HID_ * E_);
    k_castw<<<(NLAY * E_ * HID_ + 255) / 256, 256, 0, s1>>>(w_mlp2, wM2, NLAY * E_ * HID_);
    k_init_tables<<<(W_ * 184 + 255) / 256, 256, 0, s1>>>();
    k_zero_cfh<<<(LM_ * 512 * 96 / 8 + 255) / 256, 256, 0, s1>>>();
    k_cast_legfT<<<(MM_ * 184 * 96 + 255) / 256, 256, 0, s1>>>(leg_fwd);
    k_cast_leg<<<(MM_ * LM_ * 184 + 255) / 256, 256, 0, s1>>>(leg_inv, legiH);
    k_cast_dec1<<<(E_ * 264 + 255) / 256, 256, 0, s1>>>(dec_w1);
    k_castx<<<(2 * HW + 255) / 256, 256, 0, s1>>>(x);
    cudaEventRecord(evInit, s1);
    for (int i = 0; i < NLAY; i++) {
        k_buildA2_t<<<gB2, bB2, 0, s1>>>(w_spec_r + (long)i * E_ * E_ * LM_,
                                         w_spec_i + (long)i * E_ * E_ * LM_, i);
        cudaEventRecord(evA2[i], s1);
    }

    // ---- main: encoder ----
    k_enc1<<<(HW / 2 + 255) / 256, 256>>>(x, enc_w1);
    cudaStreamWaitEvent(0, evW, 0);
    k_hgemm<0, false, true, true, true><<<gE, 256, SMEMSZ>>>(wEnc2, hBh, hA, pos, hAh,
                                                             nullptr, E_, HW, E_, E_, 0, 0, 0);
    cudaEventRecord(evL[0], 0);
    cudaStreamWaitEvent(0, evInit, 0);

    for (int i = 0; i < NLAY; i++) {
        // side s2: Ph = fp16( w_inner[i] @ hAh ), concurrent with spectral chain
        cudaStreamWaitEvent(s2, evL[i], 0);
        if (i == 0) cudaStreamWaitEvent(s2, evInit, 0);
        k_hgemm<0, false, false, false, true><<<gE, 256, SMEMSZ, s2>>>(
            wInn + (long)i * E_ * E_, hAh, nullptr, nullptr, Ph, nullptr,
            E_, HW, E_, E_, 0, 0, 0);
        cudaEventRecord(evP[i], s2);

        // main: spectral chain
        k_hgemm<1, false, false, false, false><<<gRF, 256, SMEMSZ>>>(
            hAh, Fh, nullptr, nullptr, nullptr, nullptr, 46080, 184, W_, W_, 0, 0, 0);
        k_hgemm<2, false, false, false, false><<<gLF, 256, SMEMSZ>>>(
            xfh, legfT, nullptr, nullptr, nullptr, nullptr, 512, 96, H_, 184,
            (long)512 * 184, (long)184 * 96, 0);
        cudaStreamWaitEvent(0, evA2[i], 0);
        k_hgemm<3, false, false, false, false><<<gSP, 256, SMEMSZ>>>(
            A2 + (long)i * LM_ * 512 * 512, cfh, nullptr, nullptr, nullptr, nullptr,
            512, 96, 512, 512, (long)512 * 512, (long)512 * 96, 0);
        k_hgemm<4, false, false, false, false><<<gLI, 256, SMEMSZ>>>(
            cf2h, legiH, nullptr, nullptr, nullptr, nullptr, 512, 184, LM_, 96,
            (long)512 * 96, (long)LM_ * 184, 0);
        // irfft (ATRANS A) + inner skip fused: hBh = fp16( irfft(xf2h) + Ph )
        cudaStreamWaitEvent(0, evP[i], 0);
        k_hgemm<0, false, false, false, true, true, true><<<gIR, 256, SMEMSZ>>>(
            xf2h, Gih, nullptr, nullptr, hBh, Ph, 46080, W_, 182, 46080, 0, 0, 0);
        // t_h = fp16( gelu(w_mlp1 @ hBh) )
        k_hgemm<0, true, false, false, true><<<gH, 256, SMEMSZ>>>(
            wM1 + (long)i * HID_ * E_, hBh, nullptr, nullptr, tH, nullptr,
            HID_, HW, E_, E_, 0, 0, 0);
        // hA(+hAh) = w_mlp2 @ t_h + hA  (last layer: fp16 only)
        if (i + 1 < NLAY)
            k_hgemm<0, false, true, true, true><<<gE, 256, SMEMSZ>>>(
                wM2 + (long)i * E_ * HID_, tH, hA, hA, hAh, nullptr,
                E_, HW, HID_, HID_, 0, 0, 0);
        else
            k_hgemm<0, false, true, false, true><<<gE, 256, SMEMSZ>>>(
                wM2 + (long)i * E_ * HID_, tH, nullptr, hA, hAh, nullptr,
                E_, HW, HID_, HID_, 0, 0, 0);
        if (i + 1 < NLAY) cudaEventRecord(evL[i + 1], 0);
    }

    k_hgemm<0, true, false, false, true><<<gE, 256, SMEMSZ>>>(wDec1, hAh, nullptr, nullptr,
                                                              tH, nullptr, E_, HW, 258, 264, 0, 0, 0);
    k_dec2<<<(HW / 2 + 255) / 256, 256>>>(dec_w2, out);
}

// round 15
// speedup vs baseline: 1.3081x; 1.0106x over previous
#include <cuda_runtime.h>
#include <cuda_fp16.h>
#include <math.h>

#define HW   64800
#define E_   256
#define NLAY 4
#define LM_  90
#define MM_  91
#define HID_ 512
#define H_   180
#define W_   360
#define STG  3
#define ASZ  (128 * 72)
#define BSZ  (64 * 136)
#define SMEMSZ (STG * (ASZ + BSZ) * 2)

// ---------------- scratch (device globals) ----------------
__device__ float  g_hA[E_ * HW];           // fp32 h (residual)
__device__ __half g_P_h[E_ * HW];          // fp16 inner-skip product (side stream)
__device__ __half g_hA_h[(E_ + 2) * HW];   // fp16 h; rows 256,257 = raw x
__device__ __half g_hB_h[E_ * HW];
__device__ __half g_t_h [HID_ * HW];
__device__ __half g_xfh [MM_ * 512 * 184]; // rfft out: [m][2c+ri][y pad184]
__device__ __half g_cfh [LM_ * 512 * 96];  // legfwd out: [l][2c+ri][m] (m pad 96)
__device__ __half g_cf2h[MM_ * 512 * 96];  // spectral out: [m][o2][l] (l pad 96)
__device__ __half g_xf2h[184 * 46080];     // leginv out: [2m+ri][(o*180+y)]  (k-major)
__device__ __half g_F_h [W_ * 184];        // rfft DFT [x][2m+ri]
__device__ __half g_Gi_h[182 * W_];        // irfft DFT [2m+ri][x]
__device__ __half g_legfT_h[MM_ * 184 * 96];            // fwd Legendre, [m][y pad184][l pad96]
__device__ __half g_legi_h[MM_ * LM_ * 184];            // inv Legendre, [m][l][h pad184]
__device__ __half g_A2[NLAY][LM_ * 512 * 512];  // spectral fp16 weights, all layers
// fp16 weights
__device__ __half g_w_enc2[E_ * E_];
__device__ __half g_w_inner[NLAY * E_ * E_];
__device__ __half g_w_mlp1[NLAY * HID_ * E_];
__device__ __half g_w_mlp2[NLAY * E_ * HID_];
__device__ __half g_w_dec1[E_ * 264];

__device__ __forceinline__ float gelu_f(float v) {
    return 0.5f * v * (1.0f + erff(v * 0.7071067811865475f));
}
__device__ __forceinline__ unsigned smem_u32(const void* p) {
    return (unsigned)__cvta_generic_to_shared(p);
}
__device__ __forceinline__ void cp16(void* s, const void* g, bool p) {
    unsigned sa = smem_u32(s);
    asm volatile("cp.async.cg.shared.global [%0],[%1],16,%2;\n"
                 :: "r"(sa), "l"(g), "r"(p ? 16 : 0));
}

// ---------------- DFT tables ----------------
__global__ void k_init_tables() {
    int idx = blockIdx.x * blockDim.x + threadIdx.x;
    if (idx < W_ * 184) {
        int x = idx / 184, col = idx % 184;
        float v = 0.f;
        if (col < 182) {
            int m = col >> 1, ri = col & 1;
            int r = (m * x) % W_;
            double s, c;
            sincospi((double)r / 180.0, &s, &c);
            v = ri ? (float)(-s) : (float)c;
        }
        g_F_h[idx] = __float2half(v);
    }
    if (idx < 182 * W_) {
        int k = idx / W_, x = idx % W_;
        int m = k >> 1, ri = k & 1;
        int r = (m * x) % W_;
        double s, c;
        sincospi((double)r / 180.0, &s, &c);
        double sc = (m == 0) ? (1.0 / 360.0) : (2.0 / 360.0);
        g_Gi_h[idx] = __float2half(ri ? (float)(-sc * s) : (float)(sc * c));
    }
}

__global__ void k_zero_cfh() {
    int i = blockIdx.x * blockDim.x + threadIdx.x;
    if (i < LM_ * 512 * 96 / 8) ((uint4*)g_cfh)[i] = make_uint4(0, 0, 0, 0);
}

// fwd Legendre transposed: legfT[m][y][l] = legf[m][l][y], zero-padded (y->184, l->96)
__global__ void k_cast_legfT(const float* __restrict__ s) {
    int i = blockIdx.x * blockDim.x + threadIdx.x;
    if (i >= MM_ * 184 * 96) return;
    int l = i % 96, y = (i / 96) % 184, m = i / (96 * 184);
    float v = (l < LM_ && y < H_) ? s[((long)m * LM_ + l) * H_ + y] : 0.f;
    g_legfT_h[i] = __float2half(v);
}

// inv Legendre: [m][l][h<180] -> fp16 [m][l][184], pad 0
__global__ void k_cast_leg(const float* __restrict__ s, __half* __restrict__ d) {
    int i = blockIdx.x * blockDim.x + threadIdx.x;
    if (i >= MM_ * LM_ * 184) return;
    int col = i % 184, row = i / 184;
    d[i] = (col < H_) ? __float2half(s[row * H_ + col]) : __half(0);
}

// transpose-tiled spectral weight build
__global__ void k_buildA2_t(const float* __restrict__ wr, const float* __restrict__ wi, int slot) {
    int o  = blockIdx.z;
    int c0 = blockIdx.x * 32;
    int l0 = blockIdx.y * 32;
    __shared__ float sr[32][33], si[32][33];
    int tx = threadIdx.x, ty = threadIdx.y;
    #pragma unroll
    for (int i = 0; i < 32; i += 8) {
        int c = c0 + ty + i, l = l0 + tx;
        long base = ((long)o * E_ + c) * LM_ + l;
        bool ok = (l < LM_);
        sr[ty + i][tx] = ok ? wr[base] : 0.f;
        si[ty + i][tx] = ok ? wi[base] : 0.f;
    }
    __syncthreads();
    int c = c0 + tx;
    #pragma unroll
    for (int j = 0; j < 32; j += 8) {
        int l = l0 + ty + j;
        if (l >= LM_) break;
        float r  = sr[tx][ty + j];
        float im = si[tx][ty + j];
        long b0 = ((long)l * 512 + o) * 512 + 2 * c;
        long b1 = ((long)l * 512 + o + 256) * 512 + 2 * c;
        *(__half2*)&g_A2[slot][b0] = __floats2half2_rn(r, -im);
        *(__half2*)&g_A2[slot][b1] = __floats2half2_rn(im, r);
    }
}

// ---------------- casts ----------------
__global__ void k_castw(const float* __restrict__ s, __half* __restrict__ d, int n) {
    int i = blockIdx.x * blockDim.x + threadIdx.x;
    if (i < n) d[i] = __float2half(s[i]);
}
__global__ void k_cast_dec1(const float* __restrict__ s) {
    int i = blockIdx.x * blockDim.x + threadIdx.x;
    if (i >= E_ * 264) return;
    int r = i / 264, c = i % 264;
    g_w_dec1[i] = (c < 258) ? __float2half(s[r * 258 + c]) : __half(0);
}
__global__ void k_castx(const float* __restrict__ x) {
    int i = blockIdx.x * blockDim.x + threadIdx.x;
    if (i < 2 * HW) g_hA_h[E_ * HW + i] = __float2half(x[i]);
}

// encoder stage 1: 2 pixels/thread, half2 stores
__global__ void k_enc1(const float* __restrict__ x, const float* __restrict__ w) {
    int p = (blockIdx.x * blockDim.x + threadIdx.x) * 2;
    if (p >= HW) return;
    float x0a = x[p],      x1a = x[HW + p];
    float x0b = x[p + 1],  x1b = x[HW + p + 1];
    #pragma unroll 4
    for (int e = 0; e < E_; e++) {
        float w0 = w[2 * e], w1 = w[2 * e + 1];
        float va = gelu_f(w0 * x0a + w1 * x1a);
        float vb = gelu_f(w0 * x0b + w1 * x1b);
        *(__half2*)&g_hB_h[e * HW + p] = __floats2half2_rn(va, vb);
    }
}

// ---------------- fp16 tensor-core GEMM, BK=64, 3-stage cp.async ----------------
// MODE 0: std epilogue. 1: rfft -> g_xfh [m][c2][y]. 2: legfwd -> g_cfh.
// 3: spectral -> g_cf2h. 4: leginv -> g_xf2h [k][(o,y)] coalesced.
// ADDH: add fp16 ADDh tensor. ATRANS: A stored K-major [K][M].
// T64: 128x64 tile (warps 4x2) for narrow-N stages.
template <int MODE, bool GELU, bool ADDF, bool WF32, bool WF16,
          bool ADDH = false, bool ATRANS = false, bool T64 = false>
__global__ __launch_bounds__(256, 2) void k_hgemm(
    const __half* __restrict__ A, const __half* __restrict__ B,
    float* __restrict__ C, const float* __restrict__ ADD, __half* __restrict__ Ch,
    const __half* __restrict__ ADDh,
    int M, int N, int K, int lda, long sA, long sB, long sC) {
    extern __shared__ __half dsm[];
    typedef __half (*AsT)[128][72];
    typedef __half (*AsTt)[64][136];
    typedef __half (*BsT)[64][136];
    AsT  As  = (AsT)dsm;
    AsTt As2 = (AsTt)dsm;                       // overlay (ATRANS layout)
    BsT  Bs  = (BsT)(dsm + STG * ASZ);
    constexpr int BN = T64 ? 64 : 128;
    constexpr int MT = T64 ? 2 : 4;             // 16-row m-tiles per warp
    const int tid = threadIdx.x, lane = tid & 31, wid = tid >> 5;
    const int wm = T64 ? (wid >> 1) : (wid >> 2);
    const int wn = T64 ? (wid & 1) : (wid & 3);
    const int bm = blockIdx.y * 128, bn = blockIdx.x * BN;
    const int z = blockIdx.z;
    A += (long)z * sA;
    B += (long)z * sB;
    if (WF32 && MODE == 0) C += (long)z * sC;

    #define LOAD_STAGE(k0, buf)                                                     \
        {                                                                           \
            if (ATRANS) {                                                           \
                _Pragma("unroll")                                                   \
                for (int i = 0; i < 4; i++) {                                       \
                    int idx = tid + i * 256;                                        \
                    int kk = idx >> 4, moff = (idx & 15) * 8;                       \
                    int gk = (k0) + kk;                                             \
                    bool pa = (gk < K);                                             \
                    cp16(&As2[buf][kk][moff],                                       \
                         pa ? A + (long)gk * lda + bm + moff : A, pa);              \
                }                                                                   \
            } else {                                                                \
                _Pragma("unroll")                                                   \
                for (int i = 0; i < 4; i++) {                                       \
                    int idx = tid + i * 256;                                        \
                    int r = idx >> 3, col = (idx & 7) * 8;                          \
                    bool pa = ((k0) + col + 8 <= lda);                              \
                    cp16(&As[buf][r][col],                                          \
                         pa ? A + (long)(bm + r) * lda + (k0) + col : A, pa);       \
                }                                                                   \
            }                                                                       \
            if (T64) {                                                              \
                _Pragma("unroll")                                                   \
                for (int i = 0; i < 2; i++) {                                       \
                    int idx = tid + i * 256;                                        \
                    int kk = idx >> 3, noff = (idx & 7) * 8;                        \
                    int gk = (k0) + kk, gn = bn + noff;                             \
                    bool pb = (gk < K && gn + 8 <= N);                              \
                    cp16(&Bs[buf][kk][noff], pb ? B + (long)gk * N + gn : B, pb);   \
                }                                                                   \
            } else {                                                                \
                _Pragma("unroll")                                                   \
                for (int i = 0; i < 4; i++) {                                       \
                    int idx = tid + i * 256;                                        \
                    int kk = idx >> 4, noff = (idx & 15) * 8;                       \
                    int gk = (k0) + kk, gn = bn + noff;                             \
                    bool pb = (gk < K && gn + 8 <= N);                              \
                    cp16(&Bs[buf][kk][noff], pb ? B + (long)gk * N + gn : B, pb);   \
                }                                                                   \
            }                                                                       \
            asm volatile("cp.async.commit_group;\n" ::);                            \
        }

    float acc[MT][4][4];
    #pragma unroll
    for (int i = 0; i < MT; i++)
        #pragma unroll
        for (int j = 0; j < 4; j++)
            #pragma unroll
            for (int q = 0; q < 4; q++) acc[i][j][q] = 0.f;

    LOAD_STAGE(0, 0)
    LOAD_STAGE(64, 1)
    LOAD_STAGE(128, 2)

    const int nslab = (K + 63) / 64;
    const int mrow0 = wm * (MT * 16);
    for (int it = 0; it < nslab; it++) {
        asm volatile("cp.async.wait_group 2;\n" ::);
        __syncthreads();
        const int buf = it % 3;
        #pragma unroll
        for (int ks = 0; ks < 64; ks += 16) {
            unsigned a[MT][4], b[4][2];
            #pragma unroll
            for (int mt = 0; mt < MT; mt++) {
                if (ATRANS) {
                    int m0 = mrow0 + mt * 16;
                    int krow = ks + ((lane >> 4) & 1) * 8 + (lane & 7);
                    int mcol = m0 + ((lane >> 3) & 1) * 8;
                    unsigned addr = smem_u32(&As2[buf][krow][mcol]);
                    asm volatile("ldmatrix.sync.aligned.m8n8.x4.trans.shared.b16 {%0,%1,%2,%3},[%4];"
                                 : "=r"(a[mt][0]), "=r"(a[mt][1]), "=r"(a[mt][2]), "=r"(a[mt][3])
                                 : "r"(addr));
                } else {
                    unsigned addr = smem_u32(&As[buf][mrow0 + mt * 16 + (lane & 15)][ks + 8 * (lane >> 4)]);
                    asm volatile("ldmatrix.sync.aligned.m8n8.x4.shared.b16 {%0,%1,%2,%3},[%4];"
                                 : "=r"(a[mt][0]), "=r"(a[mt][1]), "=r"(a[mt][2]), "=r"(a[mt][3])
                                 : "r"(addr));
                }
            }
            #pragma unroll
            for (int nt = 0; nt < 4; nt++) {
                unsigned addr = smem_u32(&Bs[buf][ks + (lane & 15)][wn * 32 + nt * 8]);
                asm volatile("ldmatrix.sync.aligned.m8n8.x2.trans.shared.b16 {%0,%1},[%2];"
                             : "=r"(b[nt][0]), "=r"(b[nt][1])
                             : "r"(addr));
            }
            #pragma unroll
            for (int mt = 0; mt < MT; mt++)
                #pragma unroll
                for (int nt = 0; nt < 4; nt++)
                    asm volatile(
                        "mma.sync.aligned.m16n8k16.row.col.f32.f16.f16.f32 "
                        "{%0,%1,%2,%3},{%4,%5,%6,%7},{%8,%9},{%0,%1,%2,%3};"
                        : "+f"(acc[mt][nt][0]), "+f"(acc[mt][nt][1]),
                          "+f"(acc[mt][nt][2]), "+f"(acc[mt][nt][3])
                        : "r"(a[mt][0]), "r"(a[mt][1]), "r"(a[mt][2]), "r"(a[mt][3]),
                          "r"(b[nt][0]), "r"(b[nt][1]));
        }
        __syncthreads();
        int k0n = (it + 3) * 64;
        if (k0n < K) {
            LOAD_STAGE(k0n, (it + 3) % 3)
        } else {
            asm volatile("cp.async.commit_group;\n" ::);
        }
    }
    #undef LOAD_STAGE

    const int g = lane >> 2, tq = lane & 3;
    #pragma unroll
    for (int mt = 0; mt < MT; mt++) {
        #pragma unroll
        for (int hh = 0; hh < 2; hh++) {
            int gm = bm + mrow0 + mt * 16 + g + hh * 8;
            float vv0, vv1;
            #pragma unroll
            for (int nt = 0; nt < 4; nt++) {
                int gn = bn + wn * 32 + nt * 8 + tq * 2;
                vv0 = acc[mt][nt][hh * 2 + 0];
                vv1 = acc[mt][nt][hh * 2 + 1];
                if (MODE == 1) {
                    if (gn < 2 * MM_) {
                        int m = gn >> 1;
                        int c = gm / H_, y = gm - c * H_;
                        long base = (long)m * (512 * 184) + (2 * c) * 184 + y;
                        g_xfh[base]       = __float2half(vv0);
                        g_xfh[base + 184] = __float2half(vv1);
                    }
                } else if (MODE == 2) {
                    if (gn < LM_)
                        g_cfh[((long)gn * 512 + gm) * 96 + z] = __float2half(vv0);
                    if (gn + 1 < LM_)
                        g_cfh[((long)(gn + 1) * 512 + gm) * 96 + z] = __float2half(vv1);
                } else if (MODE == 3) {
                    if (gn < MM_)
                        g_cf2h[((long)gn * 512 + gm) * 96 + z] = __float2half(vv0);
                    if (gn + 1 < MM_)
                        g_cf2h[((long)(gn + 1) * 512 + gm) * 96 + z] = __float2half(vv1);
                } else if (MODE == 4) {
                    int oo = gm & 255, ri = gm >> 8;
                    if (gn + 1 < H_) {
                        long addr = (long)(2 * z + ri) * 46080 + oo * H_ + gn;
                        *(__half2*)&g_xf2h[addr] = __floats2half2_rn(vv0, vv1);
                    }
                } else {
                    if (gm >= M || gn >= N) continue;
                    if (GELU) { vv0 = gelu_f(vv0); vv1 = gelu_f(vv1); }
                    if (ADDF) {
                        float2 ad = *(const float2*)&ADD[(long)gm * N + gn];
                        vv0 += ad.x; vv1 += ad.y;
                    }
                    if (ADDH) {
                        __half2 ah = *(const __half2*)&ADDh[(long)gm * N + gn];
                        float2 af = __half22float2(ah);
                        vv0 += af.x; vv1 += af.y;
                    }
                    if (WF32) *(float2*)&C[(long)gm * N + gn] = make_float2(vv0, vv1);
                    if (WF16) *(__half2*)&Ch[(long)gm * N + gn] = __floats2half2_rn(vv0, vv1);
                }
            }
        }
    }
}

// decoder stage 2: 2 pixels/thread, half2 loads
__global__ void k_dec2(const float* __restrict__ w, float* __restrict__ out) {
    int p = (blockIdx.x * blockDim.x + threadIdx.x) * 2;
    if (p >= HW) return;
    float a0 = 0.f, a1 = 0.f, b0 = 0.f, b1 = 0.f;
    #pragma unroll 4
    for (int c = 0; c < E_; c++) {
        __half2 vh = *(const __half2*)&g_t_h[c * HW + p];
        float2 vf = __half22float2(vh);
        float w0 = w[c], w1 = w[E_ + c];
        a0 += w0 * vf.x; b0 += w0 * vf.y;
        a1 += w1 * vf.x; b1 += w1 * vf.y;
    }
    out[p] = a0;       out[p + 1] = b0;
    out[HW + p] = a1;  out[HW + p + 1] = b1;
}

extern "C" void kernel_launch(void* const* d_in, const int* in_sizes, int n_in,
                              void* d_out, int out_size) {
    const float* x        = (const float*)d_in[0];
    const float* enc_w1   = (const float*)d_in[1];
    const float* enc_w2   = (const float*)d_in[2];
    const float* pos      = (const float*)d_in[3];
    const float* leg_fwd  = (const float*)d_in[4];
    const float* leg_inv  = (const float*)d_in[5];
    const float* w_spec_r = (const float*)d_in[6];
    const float* w_spec_i = (const float*)d_in[7];
    const float* w_inner  = (const float*)d_in[8];
    const float* w_mlp1   = (const float*)d_in[9];
    const float* w_mlp2   = (const float*)d_in[10];
    const float* dec_w1   = (const float*)d_in[11];
    const float* dec_w2   = (const float*)d_in[12];
    float* out = (float*)d_out;

    float* hA;
    __half *Ph, *hAh, *hBh, *tH, *wEnc2, *wInn, *wM1, *wM2, *wDec1;
    __half *Fh, *Gih, *xfh, *cfh, *cf2h, *xf2h, *legfT, *legiH, *A2;
    cudaGetSymbolAddress((void**)&hA, g_hA);
    cudaGetSymbolAddress((void**)&Ph, g_P_h);
    cudaGetSymbolAddress((void**)&hAh, g_hA_h);
    cudaGetSymbolAddress((void**)&hBh, g_hB_h);
    cudaGetSymbolAddress((void**)&tH, g_t_h);
    cudaGetSymbolAddress((void**)&wEnc2, g_w_enc2);
    cudaGetSymbolAddress((void**)&wInn, g_w_inner);
    cudaGetSymbolAddress((void**)&wM1, g_w_mlp1);
    cudaGetSymbolAddress((void**)&wM2, g_w_mlp2);
    cudaGetSymbolAddress((void**)&wDec1, g_w_dec1);
    cudaGetSymbolAddress((void**)&Fh, g_F_h);
    cudaGetSymbolAddress((void**)&Gih, g_Gi_h);
    cudaGetSymbolAddress((void**)&xfh, g_xfh);
    cudaGetSymbolAddress((void**)&cfh, g_cfh);
    cudaGetSymbolAddress((void**)&cf2h, g_cf2h);
    cudaGetSymbolAddress((void**)&xf2h, g_xf2h);
    cudaGetSymbolAddress((void**)&legfT, g_legfT_h);
    cudaGetSymbolAddress((void**)&legiH, g_legi_h);
    cudaGetSymbolAddress((void**)&A2, g_A2);

    cudaFuncSetAttribute(k_hgemm<0, false, true,  true,  true >, cudaFuncAttributeMaxDynamicSharedMemorySize, SMEMSZ);
    cudaFuncSetAttribute(k_hgemm<0, false, true,  false, true >, cudaFuncAttributeMaxDynamicSharedMemorySize, SMEMSZ);
    cudaFuncSetAttribute(k_hgemm<0, true,  false, false, true >, cudaFuncAttributeMaxDynamicSharedMemorySize, SMEMSZ);
    cudaFuncSetAttribute(k_hgemm<0, false, false, false, true >, cudaFuncAttributeMaxDynamicSharedMemorySize, SMEMSZ);
    cudaFuncSetAttribute(k_hgemm<0, false, false, false, true, true, true>, cudaFuncAttributeMaxDynamicSharedMemorySize, SMEMSZ);
    cudaFuncSetAttribute(k_hgemm<1, false, false, false, false, false, false, true>, cudaFuncAttributeMaxDynamicSharedMemorySize, SMEMSZ);
    cudaFuncSetAttribute(k_hgemm<2, false, false, false, false>, cudaFuncAttributeMaxDynamicSharedMemorySize, SMEMSZ);
    cudaFuncSetAttribute(k_hgemm<3, false, false, false, false>, cudaFuncAttributeMaxDynamicSharedMemorySize, SMEMSZ);
    cudaFuncSetAttribute(k_hgemm<4, false, false, false, false, false, false, true>, cudaFuncAttributeMaxDynamicSharedMemorySize, SMEMSZ);

    static cudaStream_t s1 = nullptr, s2 = nullptr;
    static cudaEvent_t evRoot, evInit, evW, evA2[NLAY], evL[NLAY], evP[NLAY];
    if (!s1) {
        cudaStreamCreateWithFlags(&s1, cudaStreamNonBlocking);
        cudaStreamCreateWithFlags(&s2, cudaStreamNonBlocking);
        cudaEventCreateWithFlags(&evRoot, cudaEventDisableTiming);
        cudaEventCreateWithFlags(&evInit, cudaEventDisableTiming);
        cudaEventCreateWithFlags(&evW, cudaEventDisableTiming);
        for (int i = 0; i < NLAY; i++) {
            cudaEventCreateWithFlags(&evA2[i], cudaEventDisableTiming);
            cudaEventCreateWithFlags(&evL[i], cudaEventDisableTiming);
            cudaEventCreateWithFlags(&evP[i], cudaEventDisableTiming);
        }
    }

    const int NB = (HW + 127) / 128;   // 507
    dim3 gE(NB, E_ / 128);
    dim3 gH(NB, HID_ / 128);
    dim3 gRF(3, 360);                  // rfft:   M=46080, N=184, T64 tiles (3x64=192)
    dim3 gLF(1, 4, MM_);               // legfwd: M=512, N=96, batch m
    dim3 gSP(1, 4, LM_);               // spectral: M=512, N=96, batch l
    dim3 gLI(3, 4, MM_);               // leginv: M=512, N=184, T64 tiles
    dim3 gIR(3, 360);                  // irfft:  M=46080, N=360, ATRANS A
    dim3 gB2(8, 3, 256), bB2(32, 8);

    // ---- fork init stream ----
    cudaEventRecord(evRoot, 0);
    cudaStreamWaitEvent(s1, evRoot, 0);
    k_castw<<<(E_ * E_ + 255) / 256, 256, 0, s1>>>(enc_w2, wEnc2, E_ * E_);
    cudaEventRecord(evW, s1);
    k_castw<<<(NLAY * E_ * E_ + 255) / 256, 256, 0, s1>>>(w_inner, wInn, NLAY * E_ * E_);
    k_castw<<<(NLAY * HID_ * E_ + 255) / 256, 256, 0, s1>>>(w_mlp1, wM1, NLAY * HID_ * E_);
    k_castw<<<(NLAY * E_ * HID_ + 255) / 256, 256, 0, s1>>>(w_mlp2, wM2, NLAY * E_ * HID_);
    k_init_tables<<<(W_ * 184 + 255) / 256, 256, 0, s1>>>();
    k_zero_cfh<<<(LM_ * 512 * 96 / 8 + 255) / 256, 256, 0, s1>>>();
    k_cast_legfT<<<(MM_ * 184 * 96 + 255) / 256, 256, 0, s1>>>(leg_fwd);
    k_cast_leg<<<(MM_ * LM_ * 184 + 255) / 256, 256, 0, s1>>>(leg_inv, legiH);
    k_cast_dec1<<<(E_ * 264 + 255) / 256, 256, 0, s1>>>(dec_w1);
    k_castx<<<(2 * HW + 255) / 256, 256, 0, s1>>>(x);
    cudaEventRecord(evInit, s1);
    for (int i = 0; i < NLAY; i++) {
        k_buildA2_t<<<gB2, bB2, 0, s1>>>(w_spec_r + (long)i * E_ * E_ * LM_,
                                         w_spec_i + (long)i * E_ * E_ * LM_, i);
        cudaEventRecord(evA2[i], s1);
    }

    // ---- main: encoder ----
    k_enc1<<<(HW / 2 + 255) / 256, 256>>>(x, enc_w1);
    cudaStreamWaitEvent(0, evW, 0);
    k_hgemm<0, false, true, true, true><<<gE, 256, SMEMSZ>>>(wEnc2, hBh, hA, pos, hAh,
                                                             nullptr, E_, HW, E_, E_, 0, 0, 0);
    cudaEventRecord(evL[0], 0);
    cudaStreamWaitEvent(0, evInit, 0);

    for (int i = 0; i < NLAY; i++) {
        // side s2: Ph = fp16( w_inner[i] @ hAh ), concurrent with spectral chain
        cudaStreamWaitEvent(s2, evL[i], 0);
        if (i == 0) cudaStreamWaitEvent(s2, evInit, 0);
        k_hgemm<0, false, false, false, true><<<gE, 256, SMEMSZ, s2>>>(
            wInn + (long)i * E_ * E_, hAh, nullptr, nullptr, Ph, nullptr,
            E_, HW, E_, E_, 0, 0, 0);
        cudaEventRecord(evP[i], s2);

        // main: spectral chain
        k_hgemm<1, false, false, false, false, false, false, true><<<gRF, 256, SMEMSZ>>>(
            hAh, Fh, nullptr, nullptr, nullptr, nullptr, 46080, 184, W_, W_, 0, 0, 0);
        k_hgemm<2, false, false, false, false><<<gLF, 256, SMEMSZ>>>(
            xfh, legfT, nullptr, nullptr, nullptr, nullptr, 512, 96, H_, 184,
            (long)512 * 184, (long)184 * 96, 0);
        cudaStreamWaitEvent(0, evA2[i], 0);
        k_hgemm<3, false, false, false, false><<<gSP, 256, SMEMSZ>>>(
            A2 + (long)i * LM_ * 512 * 512, cfh, nullptr, nullptr, nullptr, nullptr,
            512, 96, 512, 512, (long)512 * 512, (long)512 * 96, 0);
        k_hgemm<4, false, false, false, false, false, false, true><<<gLI, 256, SMEMSZ>>>(
            cf2h, legiH, nullptr, nullptr, nullptr, nullptr, 512, 184, LM_, 96,
            (long)512 * 96, (long)LM_ * 184, 0);
        // irfft (ATRANS A) + inner skip fused: hBh = fp16( irfft(xf2h) + Ph )
        cudaStreamWaitEvent(0, evP[i], 0);
        k_hgemm<0, false, false, false, true, true, true><<<gIR, 256, SMEMSZ>>>(
            xf2h, Gih, nullptr, nullptr, hBh, Ph, 46080, W_, 182, 46080, 0, 0, 0);
        // t_h = fp16( gelu(w_mlp1 @ hBh) )
        k_hgemm<0, true, false, false, true><<<gH, 256, SMEMSZ>>>(
            wM1 + (long)i * HID_ * E_, hBh, nullptr, nullptr, tH, nullptr,
            HID_, HW, E_, E_, 0, 0, 0);
        // hA(+hAh) = w_mlp2 @ t_h + hA  (last layer: fp16 only)
        if (i + 1 < NLAY)
            k_hgemm<0, false, true, true, true><<<gE, 256, SMEMSZ>>>(
                wM2 + (long)i * E_ * HID_, tH, hA, hA, hAh, nullptr,
                E_, HW, HID_, HID_, 0, 0, 0);
        else
            k_hgemm<0, false, true, false, true><<<gE, 256, SMEMSZ>>>(
                wM2 + (long)i * E_ * HID_, tH, nullptr, hA, hAh, nullptr,
                E_, HW, HID_, HID_, 0, 0, 0);
        if (i + 1 < NLAY) cudaEventRecord(evL[i + 1], 0);
    }

    k_hgemm<0, true, false, false, true><<<gE, 256, SMEMSZ>>>(wDec1, hAh, nullptr, nullptr,
                                                              tH, nullptr, E_, HW, 258, 264, 0, 0, 0);
    k_dec2<<<(HW / 2 + 255) / 256, 256>>>(dec_w2, out);
}